// round 14
// baseline (speedup 1.0000x reference)
#include <cuda_runtime.h>
#include <cuda_bf16.h>
#include <cstdint>

// ---------------- problem constants ----------------
#define NBLK 148
#define NTHR 512
#define BB   256
#define NC   3072            // compact gate width (i, gg, o) -- f gate is dead
#define TT   256
#define VV   130
#define BH   (256*1024)
#define GS   (256*3072)
#define ASLAB 131072         // uints per activation fragment slab (256x1024/2)
#define WNF  384             // n-frags per z for 3072-row weight matrices
#define WZS  (WNF*4096)      // uints per z for 3072-row weights

// ---------------- persistent device scratch (fp32) ----------------
__device__ float d_cT   [16*256*512];
__device__ float d_cPrev[16*256*512];
__device__ float d_hid  [16*256*1024];
__device__ float d_A1   [3*16*256*3072];
__device__ float d_CU   [16*256*3072];
__device__ float d_C2   [3*16*256*3072];
__device__ float d_E    [3*130*3072];
__device__ float d_nb1  [3*3072];
__device__ float d_s    [3*256*3072];
__device__ float d_sn   [2*256*3072];
__device__ float d_g    [3*256*3072];

// ---------------- fragment-layout weights (hi/lo split bf16, packed uints) --
__device__ unsigned d_W1hhf_h[3*WZS], d_W1hhf_l[3*WZS];
__device__ unsigned d_cWihf_h[3*WZS], d_cWihf_l[3*WZS];
__device__ unsigned d_cWhhf_h[1*WZS], d_cWhhf_l[1*WZS];
__device__ unsigned d_W2ihf_h[3*WZS], d_W2ihf_l[3*WZS];
__device__ unsigned d_W2hhf_h[3*WZS], d_W2hhf_l[3*WZS];
__device__ unsigned d_outWf_h[3*32*4096], d_outWf_l[3*32*4096];  // padded 32 frags

// ---------------- fragment-layout activations ----------------
__device__ unsigned d_h1f_h [3*ASLAB], d_h1f_l [3*ASLAB];
__device__ unsigned d_h2f_h [3*ASLAB], d_h2f_l [3*ASLAB];
__device__ unsigned d_ctxf_h[3*ASLAB], d_ctxf_l[3*ASLAB];
__device__ unsigned d_uof_h [3*ASLAB], d_uof_l [3*ASLAB];
__device__ unsigned d_unf_h [2*ASLAB], d_unf_l [2*ASLAB];

// ---------------- grid barrier (replay-safe, sense via generation) ----------
__device__ unsigned int g_arrive;
__device__ unsigned int g_gen;

__device__ __forceinline__ void gsync()
{
    __threadfence();
    __syncthreads();
    if (threadIdx.x == 0) {
        volatile unsigned int* vg = &g_gen;
        unsigned int g = *vg;
        if (atomicAdd(&g_arrive, 1u) == (unsigned)(gridDim.x - 1)) {
            g_arrive = 0;
            __threadfence();
            *vg = g + 1u;
        } else {
            while (*vg == g) __nanosleep(32);
        }
        __threadfence();
    }
    __syncthreads();
}

// half-block barrier (256 threads), id 1 or 2
__device__ __forceinline__ void hsync(int id)
{
    asm volatile("bar.sync %0, 256;" :: "r"(id) : "memory");
}

// ---------------- f32x2 helpers (preamble FFMA2 path) ----------------
__device__ __forceinline__ void fma2(unsigned long long &c, unsigned long long a,
                                     unsigned long long b) {
    asm("fma.rn.f32x2 %0, %1, %2, %0;" : "+l"(c) : "l"(a), "l"(b));
}
__device__ __forceinline__ void unpack2(unsigned long long v, float &lo, float &hi) {
    asm("mov.b64 {%0, %1}, %2;" : "=f"(lo), "=f"(hi) : "l"(v));
}
__device__ __forceinline__ unsigned long long dup2(float a) {
    unsigned long long r;
    asm("mov.b64 %0, {%1, %1};" : "=l"(r) : "f"(a));
    return r;
}

// ---------------- mma / async helpers ----------------
__device__ __forceinline__ void mma16816(float* d, const unsigned* a, const unsigned* b) {
    asm volatile("mma.sync.aligned.m16n8k16.row.col.f32.bf16.bf16.f32 "
                 "{%0,%1,%2,%3},{%4,%5,%6,%7},{%8,%9},{%0,%1,%2,%3};"
                 : "+f"(d[0]), "+f"(d[1]), "+f"(d[2]), "+f"(d[3])
                 : "r"(a[0]), "r"(a[1]), "r"(a[2]), "r"(a[3]), "r"(b[0]), "r"(b[1]));
}
__device__ __forceinline__ uint2 lds64(unsigned a) {
    uint2 r;
    asm volatile("ld.shared.v2.u32 {%0,%1},[%2];" : "=r"(r.x), "=r"(r.y) : "r"(a));
    return r;
}
__device__ __forceinline__ void cpasync16(unsigned dst, const void* src) {
    asm volatile("cp.async.cg.shared.global [%0],[%1],16;" :: "r"(dst), "l"(src) : "memory");
}
__device__ __forceinline__ void cpcommit() {
    asm volatile("cp.async.commit_group;" ::: "memory");
}
__device__ __forceinline__ void cpwait1() {
    asm volatile("cp.async.wait_group 1;" ::: "memory");
}

// ---------------- split/pack helpers ----------------
__device__ __forceinline__ void pack_split(float v0, float v1, unsigned& hi, unsigned& lo)
{
    __nv_bfloat16 h0 = __float2bfloat16(v0);
    __nv_bfloat16 h1 = __float2bfloat16(v1);
    __nv_bfloat16 l0 = __float2bfloat16(v0 - __bfloat162float(h0));
    __nv_bfloat16 l1 = __float2bfloat16(v1 - __bfloat162float(h1));
    hi = (unsigned)__bfloat16_as_ushort(h0) | ((unsigned)__bfloat16_as_ushort(h1) << 16);
    lo = (unsigned)__bfloat16_as_ushort(l0) | ((unsigned)__bfloat16_as_ushort(l1) << 16);
}

__device__ __forceinline__ float gatef(float gi, float gg, float go)
{
    float si = 1.f / (1.f + expf(-gi));
    float so = 1.f / (1.f + expf(-go));
    return so * tanhf(si * tanhf(gg));
}

// ================= preamble FFMA2 GEMM (512-thread) =================
struct GP {
    const float* A;  long long lda,  Az;
    const float* B;  long long ldb,  Bz;
    int K, M, N, zc, compact, epi;
    float* C; long long ldc, Cz;
    const float* bias; long long biasz; int biasCompact;
};

__device__ __forceinline__ void run_mm(const float* A, long long lda, int M, int m0,
                                       const float* Bb, long long ldb, int N, int n0, int K,
                                       float* As, float* Bs,
                                       unsigned long long (*acc)[4],
                                       int tid, int tx, int ty)
{
    int nIter = K >> 4;
    int row = tid >> 2, kq = (tid & 3) << 2;
    for (int it = 0; it < nIter; it++) {
        int k0 = it << 4;
        float4 ra = (m0 + row < M)
            ? *(const float4*)(A + (long long)(m0 + row) * lda + k0 + kq)
            : make_float4(0.f, 0.f, 0.f, 0.f);
        float4 rb = (n0 + row < N)
            ? *(const float4*)(Bb + (long long)row * ldb + k0 + kq)
            : make_float4(0.f, 0.f, 0.f, 0.f);
        __syncthreads();
        As[(kq + 0) * 128 + row] = ra.x;
        As[(kq + 1) * 128 + row] = ra.y;
        As[(kq + 2) * 128 + row] = ra.z;
        As[(kq + 3) * 128 + row] = ra.w;
        Bs[(kq + 0) * 128 + row] = rb.x;
        Bs[(kq + 1) * 128 + row] = rb.y;
        Bs[(kq + 2) * 128 + row] = rb.z;
        Bs[(kq + 3) * 128 + row] = rb.w;
        __syncthreads();
#pragma unroll
        for (int kk = 0; kk < 16; kk++) {
            ulonglong2 b01 = *(const ulonglong2*)&Bs[kk * 128 + tx * 8];
            ulonglong2 b23 = *(const ulonglong2*)&Bs[kk * 128 + tx * 8 + 4];
            ulonglong2 ap  = *(const ulonglong2*)&As[kk * 128 + ty * 4];
            float av[4];
            unpack2(ap.x, av[0], av[1]);
            unpack2(ap.y, av[2], av[3]);
#pragma unroll
            for (int mi = 0; mi < 4; mi++) {
                unsigned long long a2 = dup2(av[mi]);
                fma2(acc[mi][0], b01.x, a2);
                fma2(acc[mi][1], b01.y, a2);
                fma2(acc[mi][2], b23.x, a2);
                fma2(acc[mi][3], b23.y, a2);
            }
        }
    }
    __syncthreads();
}

__device__ void gemm_stage(const GP& g, float* As, float* Bs)
{
    int mT = (g.M + 127) >> 7;
    int nT = (g.N + 127) >> 7;
    int total = g.zc * mT * nT;
    int tid = threadIdx.x;
    int tx = tid & 15, ty = tid >> 4;

    for (int tile = blockIdx.x; tile < total; tile += gridDim.x) {
        int z  = tile / (mT * nT);
        int r  = tile - z * (mT * nT);
        int m0 = (r / nT) << 7;
        int n0 = (r % nT) << 7;
        int noff = (g.compact && n0 >= 1024) ? 1024 : 0;

        unsigned long long acc[4][4];
#pragma unroll
        for (int i = 0; i < 4; i++)
#pragma unroll
            for (int j = 0; j < 4; j++) acc[i][j] = 0ull;

        const float* A  = g.A + (long long)z * g.Az;
        const float* Bb = g.B + (long long)z * g.Bz + (long long)(n0 + noff) * g.ldb;
        run_mm(A, g.lda, g.M, m0, Bb, g.ldb, g.N, n0, g.K, As, Bs, acc, tid, tx, ty);

        float* C = g.C + (long long)z * g.Cz;
#pragma unroll
        for (int mi = 0; mi < 4; mi++) {
            int m = m0 + ty * 4 + mi;
            if (m >= g.M) continue;
            float cv[8];
#pragma unroll
            for (int jj = 0; jj < 4; jj++)
                unpack2(acc[mi][jj], cv[2 * jj], cv[2 * jj + 1]);
#pragma unroll
            for (int nj = 0; nj < 8; nj++) {
                int n = n0 + tx * 8 + nj;
                if (n >= g.N) continue;
                float v = cv[nj];
                if (g.bias) v += g.bias[(long long)z * g.biasz + (g.biasCompact ? (n + noff) : n)];
                if (g.epi == 1) v = tanhf(v);
                C[(long long)m * g.ldc + n] = v;
            }
        }
    }
}

// ================= fragment-direct tensor-core GEMM =================
// Two independent 256-thread halves per block; each half owns a 24KB smem
// region (3 stages x 8KB) and its own tile stream + named barrier.
// A frag slab layout: uint index = ((mf*64 + ks)*32 + lane)*4 + reg
// B frag layout:      uint index = ((nf*64 + ks)*64 + lane*2 + reg)
struct MGP {
    const unsigned *Ah, *Al;   long long Az;
    const unsigned *Bh, *Bl;   long long Bz;
    const unsigned *A2h, *A2l; long long A2z;
    const unsigned *B2h, *B2l; long long B2z;
    int M, N, zc;                               // K fixed = 1024 (64 slices)
    float* C; long long ldc, Cz;
    const float* add0; long long add0z;
    const float *add1, *add2;
    const float* bias; long long biasz; int biasCompact;
    const float* Eg;  long long Egz;
    const int*  tok;  long long tokz;  int tokstride;
};

// 64x128 tile, 8 warps (wm 0..1, wn 0..3, NT=4)
__device__ __forceinline__ void mma_runp(
    const unsigned* Ah, const unsigned* Al,
    const unsigned* Bh, const unsigned* Bl,
    int m0, int n0, float* d, unsigned sbh, int lt, int wm, int wn, int L, int barid)
{
    int mf0 = (m0 >> 4) + wm * 2;
    const unsigned* paH0 = Ah + ((long long)(mf0 + 0) * 64) * 128 + L * 4;
    const unsigned* paH1 = Ah + ((long long)(mf0 + 1) * 64) * 128 + L * 4;
    const unsigned* paL0 = Al + ((long long)(mf0 + 0) * 64) * 128 + L * 4;
    const unsigned* paL1 = Al + ((long long)(mf0 + 1) * 64) * 128 + L * 4;

    // B staging: each of 256 threads copies one hi chunk and one lo chunk.
    int sf = lt >> 4, wq = (lt & 15) * 4;
    const unsigned* gBh = Bh + ((long long)((n0 >> 3) + sf) * 64) * 64 + wq;
    const unsigned* gBl = Bl + ((long long)((n0 >> 3) + sf) * 64) * 64 + wq;
    unsigned dstB = sbh + (unsigned)((sf * 64 + wq) * 4);

#pragma unroll
    for (int s = 0; s < 2; s++) {               // prologue: stages 0,1
        cpasync16(dstB + (unsigned)(s * 8192),         gBh + s * 64);
        cpasync16(dstB + (unsigned)(s * 8192) + 4096u, gBl + s * 64);
        cpcommit();
    }
    uint4 ahC0 = *(const uint4*)(paH0);
    uint4 ahC1 = *(const uint4*)(paH1);
    uint4 alC0 = *(const uint4*)(paL0);
    uint4 alC1 = *(const uint4*)(paL1);

    for (int ks = 0; ks < 64; ks++) {
        cpwait1();                              // stage ks%3 complete
        hsync(barid);                           // half-scope visibility + reuse
        if (ks < 62) {                          // issue stage (ks+2)%3
            unsigned sB = (unsigned)(((ks + 2) % 3) * 8192);
            cpasync16(dstB + sB,          gBh + (ks + 2) * 64);
            cpasync16(dstB + sB + 4096u,  gBl + (ks + 2) * 64);
        }
        cpcommit();                             // always: group alignment

        unsigned sBase = sbh + (unsigned)((ks % 3) * 8192);
        uint2 bh[4], bl[4];
#pragma unroll
        for (int nt = 0; nt < 4; nt++) {
            unsigned f = (unsigned)(((wn * 4 + nt) * 64 + L * 2) * 4);
            bh[nt] = lds64(sBase + f);
            bl[nt] = lds64(sBase + 4096u + f);
        }
        uint4 ah0 = ahC0, ah1 = ahC1, al0 = alC0, al1 = alC1;
        if (ks < 63) {                          // register-prefetch next A slice
            ahC0 = *(const uint4*)(paH0 + (ks + 1) * 128);
            ahC1 = *(const uint4*)(paH1 + (ks + 1) * 128);
            alC0 = *(const uint4*)(paL0 + (ks + 1) * 128);
            alC1 = *(const uint4*)(paL1 + (ks + 1) * 128);
        }
#pragma unroll
        for (int nt = 0; nt < 4; nt++) {
            float* d0 = d + nt * 4;
            float* d1 = d + (4 + nt) * 4;
            mma16816(d0, (const unsigned*)&ah0, (const unsigned*)&bh[nt]);
            mma16816(d0, (const unsigned*)&ah0, (const unsigned*)&bl[nt]);
            mma16816(d0, (const unsigned*)&al0, (const unsigned*)&bh[nt]);
            mma16816(d1, (const unsigned*)&ah1, (const unsigned*)&bh[nt]);
            mma16816(d1, (const unsigned*)&ah1, (const unsigned*)&bl[nt]);
            mma16816(d1, (const unsigned*)&al1, (const unsigned*)&bh[nt]);
        }
    }
    hsync(barid);   // guard: next run's prologue overwrites stages 0,1
}

__device__ void mma_stage(const MGP& g, unsigned sb)
{
    int mT = (g.M + 63) >> 6;
    int nT = (g.N + 127) >> 7;
    int total = g.zc * mT * nT;
    int tid = threadIdx.x;
    int half = tid >> 8, lt = tid & 255;
    int w = lt >> 5, L = lt & 31;
    int wm = w >> 2, wn = w & 3;
    int barid = 1 + half;
    unsigned sbh = sb + (unsigned)(half * 24576);

    for (int slot = blockIdx.x * 2 + half; slot < total; slot += gridDim.x * 2) {
        int z  = slot / (mT * nT);
        int r  = slot - z * (mT * nT);
        int m0 = (r / nT) << 6;
        int n0 = (r % nT) << 7;

        float d[32];
#pragma unroll
        for (int i = 0; i < 32; i++) d[i] = 0.f;

        mma_runp(g.Ah + (long long)z * g.Az, g.Al + (long long)z * g.Az,
                 g.Bh + (long long)z * g.Bz, g.Bl + (long long)z * g.Bz,
                 m0, n0, d, sbh, lt, wm, wn, L, barid);
        if (g.A2h)
            mma_runp(g.A2h + (long long)z * g.A2z, g.A2l + (long long)z * g.A2z,
                     g.B2h + (long long)z * g.B2z, g.B2l + (long long)z * g.B2z,
                     m0, n0, d, sbh, lt, wm, wn, L, barid);

        float* C = g.C + (long long)z * g.Cz;
#pragma unroll
        for (int mt = 0; mt < 2; mt++) {
            int rbase = m0 + wm * 32 + mt * 16 + (L >> 2);
            int tk0 = 0, tk1 = 0;
            if (g.Eg) {
                tk0 = g.tok[(long long)z * g.tokz + (long long)rbase * g.tokstride];
                tk1 = g.tok[(long long)z * g.tokz + (long long)(rbase + 8) * g.tokstride];
            }
#pragma unroll
            for (int nt = 0; nt < 4; nt++) {
                const float* dd = d + (mt * 4 + nt) * 4;
                int cbase = n0 + wn * 32 + nt * 8 + (L & 3) * 2;
#pragma unroll
                for (int e = 0; e < 4; e++) {
                    int m = rbase + (e >= 2 ? 8 : 0);
                    int n = cbase + (e & 1);
                    if (n >= g.N || m >= g.M) continue;
                    float v = dd[e];
                    if (g.add0) v += g.add0[(long long)z * g.add0z + (long long)m * g.N + n];
                    if (g.add1) v += g.add1[(long long)m * g.N + n];
                    if (g.add2) v += g.add2[(long long)m * g.N + n];
                    if (g.bias) {
                        int nf = g.biasCompact ? (n + (n >= 1024 ? 1024 : 0)) : n;
                        v += g.bias[(long long)z * g.biasz + nf];
                    }
                    if (g.Eg)
                        v += g.Eg[(long long)z * g.Egz +
                                  (long long)(e >= 2 ? tk1 : tk0) * g.N + n];
                    C[(long long)m * g.ldc + n] = v;
                }
            }
        }
    }
}

// ---------------- elementwise stages (fragment writers) ----------------
__device__ void gate_stagef(const float* gsrc, long long gz, int zc,
                            unsigned* d0h, unsigned* d0l,
                            unsigned* d1h, unsigned* d1l)
{
    int total = zc * ASLAB;
    for (int idx = blockIdx.x * NTHR + threadIdx.x; idx < total; idx += gridDim.x * NTHR) {
        int u = idx & (ASLAB - 1);
        int z = idx >> 17;
        int r = u & 3, l = (u >> 2) & 31, ks = (u >> 7) & 63, mf = u >> 13;
        int m  = mf * 16 + (l >> 2) + (r & 1) * 8;
        int k0 = ks * 16 + ((r >> 1) & 1) * 8 + (l & 3) * 2;
        const float* gp = gsrc + (long long)z * gz + (long long)m * NC;
        float v0 = gatef(gp[k0],     gp[1024 + k0],     gp[2048 + k0]);
        float v1 = gatef(gp[k0 + 1], gp[1024 + k0 + 1], gp[2048 + k0 + 1]);
        unsigned hi, lo;
        pack_split(v0, v1, hi, lo);
        d0h[(long long)z * ASLAB + u] = hi;
        d0l[(long long)z * ASLAB + u] = lo;
        if (d1h) {
            d1h[(long long)z * ASLAB + u] = hi;
            d1l[(long long)z * ASLAB + u] = lo;
        }
    }
}

__device__ void reset_stagef(const float* hid)
{
    for (int u = blockIdx.x * NTHR + threadIdx.x; u < ASLAB; u += gridDim.x * NTHR) {
        int r = u & 3, l = (u >> 2) & 31, ks = (u >> 7) & 63, mf = u >> 13;
        int m  = mf * 16 + (l >> 2) + (r & 1) * 8;
        int k0 = ks * 16 + ((r >> 1) & 1) * 8 + (l & 3) * 2;
        const float* hp = hid + (long long)m * 1024 + k0;
        unsigned hi, lo;
        pack_split(hp[0], hp[1], hi, lo);
#pragma unroll
        for (int z = 0; z < 3; z++) {
            d_h1f_h[z * ASLAB + u] = hi; d_h1f_l[z * ASLAB + u] = lo;
            d_h2f_h[z * ASLAB + u] = hi; d_h2f_l[z * ASLAB + u] = lo;
        }
        d_ctxf_h[2 * ASLAB + u] = hi; d_ctxf_l[2 * ASLAB + u] = lo;
    }
}

__device__ void prep_stage(const float* c)
{
    for (int idx = blockIdx.x * NTHR + threadIdx.x; idx < (16 * 256 * 512);
         idx += gridDim.x * NTHR) {
        int ptr = idx >> 17;
        int rem = idx & 131071;
        int b = rem >> 9, k = rem & 511;
        d_cT[idx] = c[((b << 4) + ptr) * 512 + k];
        int pm = ptr > 0 ? ptr - 1 : 0;
        d_cPrev[idx] = c[((b << 4) + pm) * 512 + k];
    }
}

__device__ void nb1_stage(const float* emb, const float* W1ih, const float* b1)
{
    for (int idx = blockIdx.x * NTHR + threadIdx.x; idx < 3 * 3072;
         idx += gridDim.x * NTHR) {
        int i = idx / 3072, n = idx - (idx / 3072) * 3072;
        int nfull = n + (n >= 1024 ? 1024 : 0);
        const float* e = emb + (long long)i * 130 * 512;            // v = 0 row
        const float* w = W1ih + ((long long)i * 4096 + nfull) * 1024;
        float s = b1[i * 4096 + nfull];
        for (int k = 0; k < 512; k++) s += e[k] * w[k];
        d_nb1[idx] = s;
    }
}

__device__ void convw_frag(const float* src, long long sld, long long sz, int kstep,
                           int zc, int Nvalid, int NF, int compact,
                           unsigned* H, unsigned* Lo)
{
    int total = zc * NF * 4096;
    for (int idx = blockIdx.x * NTHR + threadIdx.x; idx < total;
         idx += gridDim.x * NTHR) {
        int r  = idx & 1;
        int l  = (idx >> 1) & 31;
        int ks = (idx >> 6) & 63;
        int rest = idx >> 12;
        int nf = rest % NF, z = rest / NF;
        int n = nf * 8 + (l >> 2);
        int k = ks * 16 + r * 8 + (l & 3) * 2;
        float v0 = 0.f, v1 = 0.f;
        if (n < Nvalid) {
            int nfull = compact ? (n + (n >= 1024 ? 1024 : 0)) : n;
            const float* p = src + (long long)z * sz + (long long)nfull * sld
                           + k + (long long)z * kstep;
            v0 = p[0]; v1 = p[1];
        }
        unsigned hi, lo;
        pack_split(v0, v1, hi, lo);
        H[idx] = hi; Lo[idx] = lo;
    }
}

// ---------------- the single persistent kernel ----------------
__global__ void __launch_bounds__(NTHR, 1)
mega_kernel(const float* c, const float* W1ih, const float* W1hh, const float* b1,
            const float* cWih, const float* cWhh, const float* cb,
            const float* W2ih, const float* W2hh, const float* b2,
            const float* outW, const float* outb,
            const float* hidW, const float* hidb,
            const float* emb, const int* tgt, float* out)
{
    __shared__ __align__(16) char smem_raw[49152];  // 2 halves x 24KB (3x8KB stages)
    float* As = (float*)smem_raw;
    float* Bs = (float*)(smem_raw + 8192);
    unsigned sb;
    asm("{.reg .u64 t; cvta.to.shared.u64 t, %1; cvt.u32.u64 %0, t;}"
        : "=r"(sb) : "l"(smem_raw));

    // ---- phase 0: transpose + notes0 hoist + weight fragment conversion ----
    prep_stage(c);
    nb1_stage(emb, W1ih, b1);
    convw_frag(W1hh, 1024, 4096LL * 1024, 0,    3, 3072, WNF, 1, d_W1hhf_h, d_W1hhf_l);
    convw_frag(cWih, 3072, 0,             1024, 3, 3072, WNF, 1, d_cWihf_h, d_cWihf_l);
    convw_frag(cWhh, 1024, 0,             0,    1, 3072, WNF, 1, d_cWhhf_h, d_cWhhf_l);
    convw_frag(W2ih, 1536, 4096LL * 1536, 0,    3, 3072, WNF, 1, d_W2ihf_h, d_W2ihf_l);
    convw_frag(W2hh, 1024, 4096LL * 1024, 0,    3, 3072, WNF, 1, d_W2hhf_h, d_W2hhf_l);
    convw_frag(outW, 1024, 130LL * 1024,  0,    3, 130,  32,  0, d_outWf_h, d_outWf_l);
    gsync();

    // ---- phase 1: per-bar hoisted GEMMs (FFMA2 path) ----
    { GP g = {};
        g.A = d_cPrev; g.lda = 512; g.B = hidW; g.ldb = 512;
        g.K = 512; g.M = 4096; g.N = 1024; g.zc = 1; g.epi = 1;
        g.C = d_hid; g.ldc = 1024; g.bias = hidb;
        gemm_stage(g, As, Bs); }
    { GP g = {};
        g.A = d_cT; g.lda = 512;
        g.B = W1ih + 512; g.ldb = 1024; g.Bz = 4096LL * 1024;
        g.K = 512; g.M = 4096; g.N = NC; g.zc = 3; g.compact = 1;
        g.C = d_A1; g.ldc = NC; g.Cz = 16LL * GS;
        g.bias = d_nb1; g.biasz = NC;
        gemm_stage(g, As, Bs); }
    { GP g = {};
        g.A = d_cT; g.lda = 512;
        g.B = W1ih + 4096LL * 1024 + 512; g.ldb = 1024;
        g.K = 512; g.M = 4096; g.N = NC; g.zc = 1; g.compact = 1;
        g.C = d_CU; g.ldc = NC;
        g.bias = b1 + 4096; g.biasCompact = 1;
        gemm_stage(g, As, Bs); }
    { GP g = {};
        g.A = d_cT; g.lda = 512;
        g.B = W2ih + 1024; g.ldb = 1536; g.Bz = 4096LL * 1536;
        g.K = 512; g.M = 4096; g.N = NC; g.zc = 3; g.compact = 1;
        g.C = d_C2; g.ldc = NC; g.Cz = 16LL * GS;
        g.bias = b2; g.biasz = 4096; g.biasCompact = 1;
        gemm_stage(g, As, Bs); }
    { GP g = {};
        g.A = emb; g.lda = 512;
        g.B = W1ih + 4096LL * 1024; g.ldb = 1024;
        g.K = 512; g.M = 390; g.N = NC; g.zc = 1; g.compact = 1;
        g.C = d_E; g.ldc = NC;
        gemm_stage(g, As, Bs); }
    gsync();

    // ---- time loop (half-split cp.async pipelined tensor-core path) ----
    for (int t = 0; t < TT; t++) {
        int ptr = t >> 4;
        if ((t & 15) == 0) {
            reset_stagef(d_hid + (long long)ptr * BH);
            gsync();
        }

        { // g = A1[.,ptr] + h1 @ W1hh^T
            MGP g = {};
            g.Ah = d_h1f_h; g.Al = d_h1f_l; g.Az = ASLAB;
            g.Bh = d_W1hhf_h; g.Bl = d_W1hhf_l; g.Bz = WZS;
            g.M = BB; g.N = NC; g.zc = 3;
            g.C = d_g; g.ldc = NC; g.Cz = GS;
            g.add0 = d_A1 + (long long)ptr * GS; g.add0z = 16LL * GS;
            mma_stage(g, sb);
        }
        gsync();
        gate_stagef(d_g, GS, 3, d_h1f_h, d_h1f_l, d_uof_h, d_uof_l);
        gsync();

        { // s[i] = uold[i] @ cWih[:, i*1024:]^T
            MGP g = {};
            g.Ah = d_uof_h; g.Al = d_uof_l; g.Az = ASLAB;
            g.Bh = d_cWihf_h; g.Bl = d_cWihf_l; g.Bz = WZS;
            g.M = BB; g.N = NC; g.zc = 3;
            g.C = d_s; g.ldc = NC; g.Cz = GS;
            mma_stage(g, sb);
        }
        { // gu[i] = E[i][tok] + CU[ptr] + uold[i] @ W1hh[1]^T   (i = 0,1)
            MGP g = {};
            g.Ah = d_uof_h; g.Al = d_uof_l; g.Az = ASLAB;
            g.Bh = d_W1hhf_h + 1LL * WZS; g.Bl = d_W1hhf_l + 1LL * WZS; g.Bz = 0;
            g.M = BB; g.N = NC; g.zc = 2;
            g.C = d_g; g.ldc = NC; g.Cz = GS;
            g.add0 = d_CU + (long long)ptr * GS; g.add0z = 0;
            g.Eg = d_E; g.Egz = 130LL * NC;
            g.tok = tgt + t; g.tokz = 65536; g.tokstride = 256;
            mma_stage(g, sb);
        }
        gsync();
        gate_stagef(d_g, GS, 2, d_unf_h, d_unf_l, (unsigned*)0, (unsigned*)0);
        gsync();

        { // sn[i] = unew[i] @ cWih[:, i*1024:]^T  (i = 0,1)
            MGP g = {};
            g.Ah = d_unf_h; g.Al = d_unf_l; g.Az = ASLAB;
            g.Bh = d_cWihf_h; g.Bl = d_cWihf_l; g.Bz = WZS;
            g.M = BB; g.N = NC; g.zc = 2;
            g.C = d_sn; g.ldc = NC; g.Cz = GS;
            mma_stage(g, sb);
        }
        { // ctx update 0
            MGP g = {};
            g.Ah = d_ctxf_h + 2LL * ASLAB; g.Al = d_ctxf_l + 2LL * ASLAB; g.Az = 0;
            g.Bh = d_cWhhf_h; g.Bl = d_cWhhf_l; g.Bz = 0;
            g.M = BB; g.N = NC; g.zc = 1;
            g.C = d_g; g.ldc = NC; g.Cz = 0;
            g.add0 = d_s; g.add0z = 0;
            g.add1 = d_s + GS; g.add2 = d_s + 2LL * GS;
            g.bias = cb; g.biasz = 0; g.biasCompact = 1;
            mma_stage(g, sb);
        }
        gsync();
        gate_stagef(d_g, 0, 1, d_ctxf_h, d_ctxf_l, (unsigned*)0, (unsigned*)0);
        gsync();

        { // ctx update 1
            MGP g = {};
            g.Ah = d_ctxf_h; g.Al = d_ctxf_l; g.Az = 0;
            g.Bh = d_cWhhf_h; g.Bl = d_cWhhf_l; g.Bz = 0;
            g.M = BB; g.N = NC; g.zc = 1;
            g.C = d_g; g.ldc = NC; g.Cz = 0;
            g.add0 = d_sn; g.add0z = 0;
            g.add1 = d_s + GS; g.add2 = d_s + 2LL * GS;
            g.bias = cb; g.biasz = 0; g.biasCompact = 1;
            mma_stage(g, sb);
        }
        gsync();
        gate_stagef(d_g, 0, 1, d_ctxf_h + ASLAB, d_ctxf_l + ASLAB,
                    (unsigned*)0, (unsigned*)0);
        gsync();

        { // ctx update 2
            MGP g = {};
            g.Ah = d_ctxf_h + 1LL * ASLAB; g.Al = d_ctxf_l + 1LL * ASLAB; g.Az = 0;
            g.Bh = d_cWhhf_h; g.Bl = d_cWhhf_l; g.Bz = 0;
            g.M = BB; g.N = NC; g.zc = 1;
            g.C = d_g; g.ldc = NC; g.Cz = 0;
            g.add0 = d_sn; g.add0z = 0;
            g.add1 = d_sn + GS; g.add2 = d_s + 2LL * GS;
            g.bias = cb; g.biasz = 0; g.biasCompact = 1;
            mma_stage(g, sb);
        }
        gsync();
        gate_stagef(d_g, 0, 1, d_ctxf_h + 2LL * ASLAB, d_ctxf_l + 2LL * ASLAB,
                    (unsigned*)0, (unsigned*)0);
        gsync();

        { // g2[i] = ctx[i] @ W2ih[i][:, :1024]^T + h2[i] @ W2hh[i]^T + C2[i][ptr]
            MGP g = {};
            g.Ah = d_ctxf_h; g.Al = d_ctxf_l; g.Az = ASLAB;
            g.Bh = d_W2ihf_h; g.Bl = d_W2ihf_l; g.Bz = WZS;
            g.A2h = d_h2f_h; g.A2l = d_h2f_l; g.A2z = ASLAB;
            g.B2h = d_W2hhf_h; g.B2l = d_W2hhf_l; g.B2z = WZS;
            g.M = BB; g.N = NC; g.zc = 3;
            g.C = d_g; g.ldc = NC; g.Cz = GS;
            g.add0 = d_C2 + (long long)ptr * GS; g.add0z = 16LL * GS;
            mma_stage(g, sb);
        }
        gsync();
        gate_stagef(d_g, GS, 3, d_h2f_h, d_h2f_l, (unsigned*)0, (unsigned*)0);
        gsync();

        { // out[i][:,t,:] = (uold[i] + h2[i]) @ outW[i]^T + outb[i]
            MGP g = {};
            g.Ah = d_uof_h; g.Al = d_uof_l; g.Az = ASLAB;
            g.Bh = d_outWf_h; g.Bl = d_outWf_l; g.Bz = 32LL * 4096;
            g.A2h = d_h2f_h; g.A2l = d_h2f_l; g.A2z = ASLAB;
            g.B2h = d_outWf_h; g.B2l = d_outWf_l; g.B2z = 32LL * 4096;
            g.M = BB; g.N = VV; g.zc = 3;
            g.C = out + (long long)t * VV; g.ldc = (long long)TT * VV;
            g.Cz = (long long)BB * TT * VV;
            g.bias = outb; g.biasz = VV;
            mma_stage(g, sb);
        }
        gsync();
    }
}

// ---------------- host ----------------
extern "C" void kernel_launch(void* const* d_in, const int* in_sizes, int n_in,
                              void* d_out, int out_size)
{
    (void)in_sizes; (void)n_in; (void)out_size;
    mega_kernel<<<NBLK, NTHR>>>(
        (const float*)d_in[0],  (const float*)d_in[1],  (const float*)d_in[2],
        (const float*)d_in[3],  (const float*)d_in[4],  (const float*)d_in[5],
        (const float*)d_in[6],  (const float*)d_in[7],  (const float*)d_in[8],
        (const float*)d_in[9],  (const float*)d_in[10], (const float*)d_in[11],
        (const float*)d_in[12], (const float*)d_in[13], (const float*)d_in[14],
        (const int*)d_in[15],   (float*)d_out);
}

// round 15
// speedup vs baseline: 1.2224x; 1.2224x over previous
#include <cuda_runtime.h>
#include <cuda_bf16.h>
#include <cstdint>

// ---------------- problem constants ----------------
#define NBLK 296
#define NTHR 256
#define BB   256
#define NC   3072            // compact gate width (i, gg, o) -- f gate is dead
#define TT   256
#define VV   130
#define BH   (256*1024)
#define GS   (256*3072)
#define ASLAB 131072         // uints per activation fragment slab (256x1024/2)
#define WNF  384             // n-frags per z for 3072-row weight matrices
#define WZS  (WNF*4096)      // uints per z for 3072-row weights

// ---------------- persistent device scratch (fp32) ----------------
__device__ float d_cT   [16*256*512];
__device__ float d_cPrev[16*256*512];
__device__ float d_hid  [16*256*1024];
__device__ float d_A1   [3*16*256*3072];
__device__ float d_CU   [16*256*3072];
__device__ float d_C2   [3*16*256*3072];
__device__ float d_E    [3*130*3072];
__device__ float d_nb1  [3*3072];
__device__ float d_s    [3*256*3072];
__device__ float d_sn   [2*256*3072];
__device__ float d_g    [3*256*3072];

// ---------------- fragment-layout weights (hi/lo split bf16, packed uints) --
__device__ unsigned d_W1hhf_h[3*WZS], d_W1hhf_l[3*WZS];
__device__ unsigned d_cWihf_h[3*WZS], d_cWihf_l[3*WZS];
__device__ unsigned d_cWhhf_h[1*WZS], d_cWhhf_l[1*WZS];
__device__ unsigned d_W2ihf_h[3*WZS], d_W2ihf_l[3*WZS];
__device__ unsigned d_W2hhf_h[3*WZS], d_W2hhf_l[3*WZS];
__device__ unsigned d_outWf_h[3*32*4096], d_outWf_l[3*32*4096];  // padded 32 frags

// ---------------- fragment-layout activations ----------------
__device__ unsigned d_h1f_h [3*ASLAB], d_h1f_l [3*ASLAB];
__device__ unsigned d_h2f_h [3*ASLAB], d_h2f_l [3*ASLAB];
__device__ unsigned d_ctxf_h[3*ASLAB], d_ctxf_l[3*ASLAB];
__device__ unsigned d_uof_h [3*ASLAB], d_uof_l [3*ASLAB];
__device__ unsigned d_unf_h [2*ASLAB], d_unf_l [2*ASLAB];

// ---------------- grid barrier (replay-safe, sense via generation) ----------
__device__ unsigned int g_arrive;
__device__ unsigned int g_gen;

__device__ __forceinline__ void gsync()
{
    __threadfence();
    __syncthreads();
    if (threadIdx.x == 0) {
        volatile unsigned int* vg = &g_gen;
        unsigned int g = *vg;
        if (atomicAdd(&g_arrive, 1u) == (unsigned)(gridDim.x - 1)) {
            g_arrive = 0;
            __threadfence();
            *vg = g + 1u;
        } else {
            while (*vg == g) __nanosleep(32);
        }
        __threadfence();
    }
    __syncthreads();
}

// ---------------- f32x2 helpers (preamble FFMA2 path) ----------------
__device__ __forceinline__ void fma2(unsigned long long &c, unsigned long long a,
                                     unsigned long long b) {
    asm("fma.rn.f32x2 %0, %1, %2, %0;" : "+l"(c) : "l"(a), "l"(b));
}
__device__ __forceinline__ void unpack2(unsigned long long v, float &lo, float &hi) {
    asm("mov.b64 {%0, %1}, %2;" : "=f"(lo), "=f"(hi) : "l"(v));
}
__device__ __forceinline__ unsigned long long dup2(float a) {
    unsigned long long r;
    asm("mov.b64 %0, {%1, %1};" : "=l"(r) : "f"(a));
    return r;
}

// ---------------- mma / async helpers ----------------
__device__ __forceinline__ void mma16816(float* d, const unsigned* a, const unsigned* b) {
    asm volatile("mma.sync.aligned.m16n8k16.row.col.f32.bf16.bf16.f32 "
                 "{%0,%1,%2,%3},{%4,%5,%6,%7},{%8,%9},{%0,%1,%2,%3};"
                 : "+f"(d[0]), "+f"(d[1]), "+f"(d[2]), "+f"(d[3])
                 : "r"(a[0]), "r"(a[1]), "r"(a[2]), "r"(a[3]), "r"(b[0]), "r"(b[1]));
}
__device__ __forceinline__ uint2 lds64(unsigned a) {
    uint2 r;
    asm volatile("ld.shared.v2.u32 {%0,%1},[%2];" : "=r"(r.x), "=r"(r.y) : "r"(a));
    return r;
}
__device__ __forceinline__ void cpasync16(unsigned dst, const void* src) {
    asm volatile("cp.async.cg.shared.global [%0],[%1],16;" :: "r"(dst), "l"(src) : "memory");
}
__device__ __forceinline__ void cpcommit() {
    asm volatile("cp.async.commit_group;" ::: "memory");
}
__device__ __forceinline__ void cpwait2() {
    asm volatile("cp.async.wait_group 2;" ::: "memory");
}

// ---------------- split/pack helpers ----------------
__device__ __forceinline__ void pack_split(float v0, float v1, unsigned& hi, unsigned& lo)
{
    __nv_bfloat16 h0 = __float2bfloat16(v0);
    __nv_bfloat16 h1 = __float2bfloat16(v1);
    __nv_bfloat16 l0 = __float2bfloat16(v0 - __bfloat162float(h0));
    __nv_bfloat16 l1 = __float2bfloat16(v1 - __bfloat162float(h1));
    hi = (unsigned)__bfloat16_as_ushort(h0) | ((unsigned)__bfloat16_as_ushort(h1) << 16);
    lo = (unsigned)__bfloat16_as_ushort(l0) | ((unsigned)__bfloat16_as_ushort(l1) << 16);
}

__device__ __forceinline__ float gatef(float gi, float gg, float go)
{
    float si = 1.f / (1.f + expf(-gi));
    float so = 1.f / (1.f + expf(-go));
    return so * tanhf(si * tanhf(gg));
}

// ================= preamble FFMA2 GEMM (256-thread, 64x128 tile) ============
struct GP {
    const float* A;  long long lda,  Az;
    const float* B;  long long ldb,  Bz;
    int K, M, N, zc, compact, epi;
    float* C; long long ldc, Cz;
    const float* bias; long long biasz; int biasCompact;
};

__device__ __forceinline__ void run_mm(const float* A, long long lda, int M, int m0,
                                       const float* Bb, long long ldb, int N, int n0, int K,
                                       float* As, float* Bs,
                                       unsigned long long (*acc)[4],
                                       int tid, int tx, int ty)
{
    int nIter = K >> 4;
    int rowA = tid >> 2, kqA = (tid & 3) << 2;
    for (int it = 0; it < nIter; it++) {
        int k0 = it << 4;
        float4 ra = (m0 + rowA < M && rowA < 64)
            ? *(const float4*)(A + (long long)(m0 + rowA) * lda + k0 + kqA)
            : make_float4(0.f, 0.f, 0.f, 0.f);
        float4 rb[2];
#pragma unroll
        for (int i = 0; i < 2; i++) {
            int j = tid + 256 * i, row = j >> 2, kq = (j & 3) << 2;
            rb[i] = (n0 + row < N)
                ? *(const float4*)(Bb + (long long)row * ldb + k0 + kq)
                : make_float4(0.f, 0.f, 0.f, 0.f);
        }
        __syncthreads();
        if (rowA < 64) {
            As[(kqA + 0) * 64 + rowA] = ra.x;
            As[(kqA + 1) * 64 + rowA] = ra.y;
            As[(kqA + 2) * 64 + rowA] = ra.z;
            As[(kqA + 3) * 64 + rowA] = ra.w;
        }
#pragma unroll
        for (int i = 0; i < 2; i++) {
            int j = tid + 256 * i, row = j >> 2, kq = (j & 3) << 2;
            Bs[(kq + 0) * 128 + row] = rb[i].x;
            Bs[(kq + 1) * 128 + row] = rb[i].y;
            Bs[(kq + 2) * 128 + row] = rb[i].z;
            Bs[(kq + 3) * 128 + row] = rb[i].w;
        }
        __syncthreads();
#pragma unroll
        for (int kk = 0; kk < 16; kk++) {
            ulonglong2 b01 = *(const ulonglong2*)&Bs[kk * 128 + tx * 8];
            ulonglong2 b23 = *(const ulonglong2*)&Bs[kk * 128 + tx * 8 + 4];
            ulonglong2 ap  = *(const ulonglong2*)&As[kk * 64 + ty * 4];
            float av[4];
            unpack2(ap.x, av[0], av[1]);
            unpack2(ap.y, av[2], av[3]);
#pragma unroll
            for (int mi = 0; mi < 4; mi++) {
                unsigned long long a2 = dup2(av[mi]);
                fma2(acc[mi][0], b01.x, a2);
                fma2(acc[mi][1], b01.y, a2);
                fma2(acc[mi][2], b23.x, a2);
                fma2(acc[mi][3], b23.y, a2);
            }
        }
        __syncthreads();
    }
}

__device__ void gemm_stage(const GP& g, float* As, float* Bs)
{
    int mT = (g.M + 63) >> 6;
    int nT = (g.N + 127) >> 7;
    int total = g.zc * mT * nT;
    int tid = threadIdx.x;
    int tx = tid & 15, ty = tid >> 4;

    for (int tile = blockIdx.x; tile < total; tile += gridDim.x) {
        int z  = tile / (mT * nT);
        int r  = tile - z * (mT * nT);
        int m0 = (r / nT) << 6;
        int n0 = (r % nT) << 7;
        int noff = (g.compact && n0 >= 1024) ? 1024 : 0;

        unsigned long long acc[4][4];
#pragma unroll
        for (int i = 0; i < 4; i++)
#pragma unroll
            for (int j = 0; j < 4; j++) acc[i][j] = 0ull;

        const float* A  = g.A + (long long)z * g.Az;
        const float* Bb = g.B + (long long)z * g.Bz + (long long)(n0 + noff) * g.ldb;
        run_mm(A, g.lda, g.M, m0, Bb, g.ldb, g.N, n0, g.K, As, Bs, acc, tid, tx, ty);

        float* C = g.C + (long long)z * g.Cz;
#pragma unroll
        for (int mi = 0; mi < 4; mi++) {
            int m = m0 + ty * 4 + mi;
            if (m >= g.M) continue;
            float cv[8];
#pragma unroll
            for (int jj = 0; jj < 4; jj++)
                unpack2(acc[mi][jj], cv[2 * jj], cv[2 * jj + 1]);
#pragma unroll
            for (int nj = 0; nj < 8; nj++) {
                int n = n0 + tx * 8 + nj;
                if (n >= g.N) continue;
                float v = cv[nj];
                if (g.bias) v += g.bias[(long long)z * g.biasz + (g.biasCompact ? (n + noff) : n)];
                if (g.epi == 1) v = tanhf(v);
                C[(long long)m * g.ldc + n] = v;
            }
        }
    }
}

// ================= fragment-direct tensor-core GEMM (R12 pipeline, 256t) ===
// A frag slab layout: uint index = ((mf*64 + ks)*32 + lane)*4 + reg
// B frag layout:      uint index = ((nf*64 + ks)*64 + lane*2 + reg)
// smem B staging: 4 stages x 8KB; stage = hi 4KB | lo 4KB
struct MGP {
    const unsigned *Ah, *Al;   long long Az;
    const unsigned *Bh, *Bl;   long long Bz;
    const unsigned *A2h, *A2l; long long A2z;
    const unsigned *B2h, *B2l; long long B2z;
    int M, N, zc;                               // K fixed = 1024 (64 slices)
    float* C; long long ldc, Cz;
    const float* add0; long long add0z;
    const float *add1, *add2;
    const float* bias; long long biasz; int biasCompact;
    const float* Eg;  long long Egz;
    const int*  tok;  long long tokz;  int tokstride;
};

// TM=64: 8 warps as 2x4 (NT=4). TM=32: 8 warps as 1x8 (NT=2).
template<int TM>
__device__ __forceinline__ void mma_runp(
    const unsigned* Ah, const unsigned* Al,
    const unsigned* Bh, const unsigned* Bl,
    int m0, int n0, float* d, unsigned sb, int tid, int wm, int wn, int L)
{
    constexpr int NT = (TM == 64) ? 4 : 2;
    int mf0 = (m0 >> 4) + wm * 2;
    const unsigned* paH0 = Ah + ((long long)(mf0 + 0) * 64) * 128 + L * 4;
    const unsigned* paH1 = Ah + ((long long)(mf0 + 1) * 64) * 128 + L * 4;
    const unsigned* paL0 = Al + ((long long)(mf0 + 0) * 64) * 128 + L * 4;
    const unsigned* paL1 = Al + ((long long)(mf0 + 1) * 64) * 128 + L * 4;

    // B staging: each of 256 threads copies one hi chunk and one lo chunk.
    int sf = tid >> 4, wq = (tid & 15) * 4;
    const unsigned* gBh = Bh + ((long long)((n0 >> 3) + sf) * 64) * 64 + wq;
    const unsigned* gBl = Bl + ((long long)((n0 >> 3) + sf) * 64) * 64 + wq;
    unsigned dstB = sb + (unsigned)((sf * 64 + wq) * 4);

#pragma unroll
    for (int s = 0; s < 3; s++) {               // prologue: stages 0..2
        cpasync16(dstB + (unsigned)(s * 8192),          gBh + s * 64);
        cpasync16(dstB + (unsigned)(s * 8192) + 4096u,  gBl + s * 64);
        cpcommit();
    }
    uint4 ahC0 = *(const uint4*)(paH0);
    uint4 ahC1 = *(const uint4*)(paH1);
    uint4 alC0 = *(const uint4*)(paL0);
    uint4 alC1 = *(const uint4*)(paL1);

    for (int ks = 0; ks < 64; ks++) {
        cpwait2();                              // stage ks complete (pending <= 2)
        __syncthreads();                        // visibility + buffer-reuse safety
        if (ks + 3 < 64) {
            unsigned sB = (unsigned)(((ks + 3) & 3) * 8192);
            cpasync16(dstB + sB,          gBh + (ks + 3) * 64);
            cpasync16(dstB + sB + 4096u,  gBl + (ks + 3) * 64);
        }
        cpcommit();                             // always: group alignment

        unsigned sBase = sb + (unsigned)((ks & 3) * 8192);
        uint2 bh[NT], bl[NT];
#pragma unroll
        for (int nt = 0; nt < NT; nt++) {
            unsigned f = (unsigned)(((wn * NT + nt) * 64 + L * 2) * 4);
            bh[nt] = lds64(sBase + f);
            bl[nt] = lds64(sBase + 4096u + f);
        }
        uint4 ah0 = ahC0, ah1 = ahC1, al0 = alC0, al1 = alC1;
        if (ks < 63) {                          // register-prefetch next A slice
            ahC0 = *(const uint4*)(paH0 + (ks + 1) * 128);
            ahC1 = *(const uint4*)(paH1 + (ks + 1) * 128);
            alC0 = *(const uint4*)(paL0 + (ks + 1) * 128);
            alC1 = *(const uint4*)(paL1 + (ks + 1) * 128);
        }
#pragma unroll
        for (int nt = 0; nt < NT; nt++) {
            float* d0 = d + nt * 4;
            float* d1 = d + (NT + nt) * 4;
            mma16816(d0, (const unsigned*)&ah0, (const unsigned*)&bh[nt]);
            mma16816(d0, (const unsigned*)&ah0, (const unsigned*)&bl[nt]);
            mma16816(d0, (const unsigned*)&al0, (const unsigned*)&bh[nt]);
            mma16816(d1, (const unsigned*)&ah1, (const unsigned*)&bh[nt]);
            mma16816(d1, (const unsigned*)&ah1, (const unsigned*)&bl[nt]);
            mma16816(d1, (const unsigned*)&al1, (const unsigned*)&bh[nt]);
        }
    }
    __syncthreads();   // guard: next run's prologue overwrites stages 0..2
}

template<int TM>
__device__ void mma_stage(const MGP& g, unsigned sb)
{
    constexpr int NT = (TM == 64) ? 4 : 2;
    constexpr int NW = NT * 8;
    int mT = (g.M + TM - 1) / TM;
    int nT = (g.N + 127) >> 7;
    int total = g.zc * mT * nT;
    int tid = threadIdx.x, w = tid >> 5, L = tid & 31;
    int wm = (TM == 64) ? (w >> 2) : 0;
    int wn = (TM == 64) ? (w & 3) : w;

    for (int tile = blockIdx.x; tile < total; tile += gridDim.x) {
        int z  = tile / (mT * nT);
        int r  = tile - z * (mT * nT);
        int m0 = (r / nT) * TM;
        int n0 = (r % nT) << 7;

        float d[2 * NT * 4];
#pragma unroll
        for (int i = 0; i < 2 * NT * 4; i++) d[i] = 0.f;

        mma_runp<TM>(g.Ah + (long long)z * g.Az, g.Al + (long long)z * g.Az,
                     g.Bh + (long long)z * g.Bz, g.Bl + (long long)z * g.Bz,
                     m0, n0, d, sb, tid, wm, wn, L);
        if (g.A2h)
            mma_runp<TM>(g.A2h + (long long)z * g.A2z, g.A2l + (long long)z * g.A2z,
                         g.B2h + (long long)z * g.B2z, g.B2l + (long long)z * g.B2z,
                         m0, n0, d, sb, tid, wm, wn, L);

        float* C = g.C + (long long)z * g.Cz;
#pragma unroll
        for (int mt = 0; mt < 2; mt++) {
            int rbase = m0 + wm * 32 + mt * 16 + (L >> 2);
            int tk0 = 0, tk1 = 0;
            if (g.Eg) {
                tk0 = g.tok[(long long)z * g.tokz + (long long)rbase * g.tokstride];
                tk1 = g.tok[(long long)z * g.tokz + (long long)(rbase + 8) * g.tokstride];
            }
#pragma unroll
            for (int nt = 0; nt < NT; nt++) {
                const float* dd = d + (mt * NT + nt) * 4;
                int cbase = n0 + wn * NW + nt * 8 + (L & 3) * 2;
#pragma unroll
                for (int e = 0; e < 4; e++) {
                    int m = rbase + (e >= 2 ? 8 : 0);
                    int n = cbase + (e & 1);
                    if (n >= g.N || m >= g.M) continue;
                    float v = dd[e];
                    if (g.add0) v += g.add0[(long long)z * g.add0z + (long long)m * g.N + n];
                    if (g.add1) v += g.add1[(long long)m * g.N + n];
                    if (g.add2) v += g.add2[(long long)m * g.N + n];
                    if (g.bias) {
                        int nf = g.biasCompact ? (n + (n >= 1024 ? 1024 : 0)) : n;
                        v += g.bias[(long long)z * g.biasz + nf];
                    }
                    if (g.Eg)
                        v += g.Eg[(long long)z * g.Egz +
                                  (long long)(e >= 2 ? tk1 : tk0) * g.N + n];
                    C[(long long)m * g.ldc + n] = v;
                }
            }
        }
    }
}

// ---------------- elementwise stages (fragment writers) ----------------
__device__ void gate_stagef(const float* gsrc, long long gz, int zc,
                            unsigned* d0h, unsigned* d0l,
                            unsigned* d1h, unsigned* d1l)
{
    int total = zc * ASLAB;
    for (int idx = blockIdx.x * NTHR + threadIdx.x; idx < total; idx += gridDim.x * NTHR) {
        int u = idx & (ASLAB - 1);
        int z = idx >> 17;
        int r = u & 3, l = (u >> 2) & 31, ks = (u >> 7) & 63, mf = u >> 13;
        int m  = mf * 16 + (l >> 2) + (r & 1) * 8;
        int k0 = ks * 16 + ((r >> 1) & 1) * 8 + (l & 3) * 2;
        const float* gp = gsrc + (long long)z * gz + (long long)m * NC;
        float v0 = gatef(gp[k0],     gp[1024 + k0],     gp[2048 + k0]);
        float v1 = gatef(gp[k0 + 1], gp[1024 + k0 + 1], gp[2048 + k0 + 1]);
        unsigned hi, lo;
        pack_split(v0, v1, hi, lo);
        d0h[(long long)z * ASLAB + u] = hi;
        d0l[(long long)z * ASLAB + u] = lo;
        if (d1h) {
            d1h[(long long)z * ASLAB + u] = hi;
            d1l[(long long)z * ASLAB + u] = lo;
        }
    }
}

__device__ void reset_stagef(const float* hid)
{
    for (int u = blockIdx.x * NTHR + threadIdx.x; u < ASLAB; u += gridDim.x * NTHR) {
        int r = u & 3, l = (u >> 2) & 31, ks = (u >> 7) & 63, mf = u >> 13;
        int m  = mf * 16 + (l >> 2) + (r & 1) * 8;
        int k0 = ks * 16 + ((r >> 1) & 1) * 8 + (l & 3) * 2;
        const float* hp = hid + (long long)m * 1024 + k0;
        unsigned hi, lo;
        pack_split(hp[0], hp[1], hi, lo);
#pragma unroll
        for (int z = 0; z < 3; z++) {
            d_h1f_h[z * ASLAB + u] = hi; d_h1f_l[z * ASLAB + u] = lo;
            d_h2f_h[z * ASLAB + u] = hi; d_h2f_l[z * ASLAB + u] = lo;
        }
        d_ctxf_h[2 * ASLAB + u] = hi; d_ctxf_l[2 * ASLAB + u] = lo;
    }
}

__device__ void prep_stage(const float* c)
{
    for (int idx = blockIdx.x * NTHR + threadIdx.x; idx < (16 * 256 * 512);
         idx += gridDim.x * NTHR) {
        int ptr = idx >> 17;
        int rem = idx & 131071;
        int b = rem >> 9, k = rem & 511;
        d_cT[idx] = c[((b << 4) + ptr) * 512 + k];
        int pm = ptr > 0 ? ptr - 1 : 0;
        d_cPrev[idx] = c[((b << 4) + pm) * 512 + k];
    }
}

__device__ void nb1_stage(const float* emb, const float* W1ih, const float* b1)
{
    for (int idx = blockIdx.x * NTHR + threadIdx.x; idx < 3 * 3072;
         idx += gridDim.x * NTHR) {
        int i = idx / 3072, n = idx - (idx / 3072) * 3072;
        int nfull = n + (n >= 1024 ? 1024 : 0);
        const float* e = emb + (long long)i * 130 * 512;            // v = 0 row
        const float* w = W1ih + ((long long)i * 4096 + nfull) * 1024;
        float s = b1[i * 4096 + nfull];
        for (int k = 0; k < 512; k++) s += e[k] * w[k];
        d_nb1[idx] = s;
    }
}

__device__ void convw_frag(const float* src, long long sld, long long sz, int kstep,
                           int zc, int Nvalid, int NF, int compact,
                           unsigned* H, unsigned* Lo)
{
    int total = zc * NF * 4096;
    for (int idx = blockIdx.x * NTHR + threadIdx.x; idx < total;
         idx += gridDim.x * NTHR) {
        int r  = idx & 1;
        int l  = (idx >> 1) & 31;
        int ks = (idx >> 6) & 63;
        int rest = idx >> 12;
        int nf = rest % NF, z = rest / NF;
        int n = nf * 8 + (l >> 2);
        int k = ks * 16 + r * 8 + (l & 3) * 2;
        float v0 = 0.f, v1 = 0.f;
        if (n < Nvalid) {
            int nfull = compact ? (n + (n >= 1024 ? 1024 : 0)) : n;
            const float* p = src + (long long)z * sz + (long long)nfull * sld
                           + k + (long long)z * kstep;
            v0 = p[0]; v1 = p[1];
        }
        unsigned hi, lo;
        pack_split(v0, v1, hi, lo);
        H[idx] = hi; Lo[idx] = lo;
    }
}

// ---------------- the single persistent kernel ----------------
__global__ void __launch_bounds__(NTHR, 2)
mega_kernel(const float* c, const float* W1ih, const float* W1hh, const float* b1,
            const float* cWih, const float* cWhh, const float* cb,
            const float* W2ih, const float* W2hh, const float* b2,
            const float* outW, const float* outb,
            const float* hidW, const float* hidb,
            const float* emb, const int* tgt, float* out)
{
    __shared__ __align__(16) char smem_raw[32768];  // 4 x 8KB B stages / preamble
    float* As = (float*)smem_raw;                   // 4KB (64x16 f32)
    float* Bs = (float*)(smem_raw + 4096);          // 8KB (128x16 f32)
    unsigned sb;
    asm("{.reg .u64 t; cvta.to.shared.u64 t, %1; cvt.u32.u64 %0, t;}"
        : "=r"(sb) : "l"(smem_raw));

    // ---- phase 0: transpose + notes0 hoist + weight fragment conversion ----
    prep_stage(c);
    nb1_stage(emb, W1ih, b1);
    convw_frag(W1hh, 1024, 4096LL * 1024, 0,    3, 3072, WNF, 1, d_W1hhf_h, d_W1hhf_l);
    convw_frag(cWih, 3072, 0,             1024, 3, 3072, WNF, 1, d_cWihf_h, d_cWihf_l);
    convw_frag(cWhh, 1024, 0,             0,    1, 3072, WNF, 1, d_cWhhf_h, d_cWhhf_l);
    convw_frag(W2ih, 1536, 4096LL * 1536, 0,    3, 3072, WNF, 1, d_W2ihf_h, d_W2ihf_l);
    convw_frag(W2hh, 1024, 4096LL * 1024, 0,    3, 3072, WNF, 1, d_W2hhf_h, d_W2hhf_l);
    convw_frag(outW, 1024, 130LL * 1024,  0,    3, 130,  32,  0, d_outWf_h, d_outWf_l);
    gsync();

    // ---- phase 1: per-bar hoisted GEMMs (FFMA2 path) ----
    { GP g = {};
        g.A = d_cPrev; g.lda = 512; g.B = hidW; g.ldb = 512;
        g.K = 512; g.M = 4096; g.N = 1024; g.zc = 1; g.epi = 1;
        g.C = d_hid; g.ldc = 1024; g.bias = hidb;
        gemm_stage(g, As, Bs); }
    { GP g = {};
        g.A = d_cT; g.lda = 512;
        g.B = W1ih + 512; g.ldb = 1024; g.Bz = 4096LL * 1024;
        g.K = 512; g.M = 4096; g.N = NC; g.zc = 3; g.compact = 1;
        g.C = d_A1; g.ldc = NC; g.Cz = 16LL * GS;
        g.bias = d_nb1; g.biasz = NC;
        gemm_stage(g, As, Bs); }
    { GP g = {};
        g.A = d_cT; g.lda = 512;
        g.B = W1ih + 4096LL * 1024 + 512; g.ldb = 1024;
        g.K = 512; g.M = 4096; g.N = NC; g.zc = 1; g.compact = 1;
        g.C = d_CU; g.ldc = NC;
        g.bias = b1 + 4096; g.biasCompact = 1;
        gemm_stage(g, As, Bs); }
    { GP g = {};
        g.A = d_cT; g.lda = 512;
        g.B = W2ih + 1024; g.ldb = 1536; g.Bz = 4096LL * 1536;
        g.K = 512; g.M = 4096; g.N = NC; g.zc = 3; g.compact = 1;
        g.C = d_C2; g.ldc = NC; g.Cz = 16LL * GS;
        g.bias = b2; g.biasz = 4096; g.biasCompact = 1;
        gemm_stage(g, As, Bs); }
    { GP g = {};
        g.A = emb; g.lda = 512;
        g.B = W1ih + 4096LL * 1024; g.ldb = 1024;
        g.K = 512; g.M = 390; g.N = NC; g.zc = 1; g.compact = 1;
        g.C = d_E; g.ldc = NC;
        gemm_stage(g, As, Bs); }
    gsync();

    // ---- time loop (2-block/SM cp.async pipelined tensor-core path) ----
    for (int t = 0; t < TT; t++) {
        int ptr = t >> 4;
        if ((t & 15) == 0) {
            reset_stagef(d_hid + (long long)ptr * BH);
            gsync();
        }

        { // g = A1[.,ptr] + h1 @ W1hh^T
            MGP g = {};
            g.Ah = d_h1f_h; g.Al = d_h1f_l; g.Az = ASLAB;
            g.Bh = d_W1hhf_h; g.Bl = d_W1hhf_l; g.Bz = WZS;
            g.M = BB; g.N = NC; g.zc = 3;
            g.C = d_g; g.ldc = NC; g.Cz = GS;
            g.add0 = d_A1 + (long long)ptr * GS; g.add0z = 16LL * GS;
            mma_stage<64>(g, sb);
        }
        gsync();
        gate_stagef(d_g, GS, 3, d_h1f_h, d_h1f_l, d_uof_h, d_uof_l);
        gsync();

        { // s[i] = uold[i] @ cWih[:, i*1024:]^T
            MGP g = {};
            g.Ah = d_uof_h; g.Al = d_uof_l; g.Az = ASLAB;
            g.Bh = d_cWihf_h; g.Bl = d_cWihf_l; g.Bz = WZS;
            g.M = BB; g.N = NC; g.zc = 3;
            g.C = d_s; g.ldc = NC; g.Cz = GS;
            mma_stage<64>(g, sb);
        }
        { // gu[i] = E[i][tok] + CU[ptr] + uold[i] @ W1hh[1]^T   (i = 0,1)
            MGP g = {};
            g.Ah = d_uof_h; g.Al = d_uof_l; g.Az = ASLAB;
            g.Bh = d_W1hhf_h + 1LL * WZS; g.Bl = d_W1hhf_l + 1LL * WZS; g.Bz = 0;
            g.M = BB; g.N = NC; g.zc = 2;
            g.C = d_g; g.ldc = NC; g.Cz = GS;
            g.add0 = d_CU + (long long)ptr * GS; g.add0z = 0;
            g.Eg = d_E; g.Egz = 130LL * NC;
            g.tok = tgt + t; g.tokz = 65536; g.tokstride = 256;
            mma_stage<64>(g, sb);
        }
        gsync();
        gate_stagef(d_g, GS, 2, d_unf_h, d_unf_l, (unsigned*)0, (unsigned*)0);
        gsync();

        { // sn[i] = unew[i] @ cWih[:, i*1024:]^T  (i = 0,1)
            MGP g = {};
            g.Ah = d_unf_h; g.Al = d_unf_l; g.Az = ASLAB;
            g.Bh = d_cWihf_h; g.Bl = d_cWihf_l; g.Bz = WZS;
            g.M = BB; g.N = NC; g.zc = 2;
            g.C = d_sn; g.ldc = NC; g.Cz = GS;
            mma_stage<64>(g, sb);
        }
        { // ctx update 0
            MGP g = {};
            g.Ah = d_ctxf_h + 2LL * ASLAB; g.Al = d_ctxf_l + 2LL * ASLAB; g.Az = 0;
            g.Bh = d_cWhhf_h; g.Bl = d_cWhhf_l; g.Bz = 0;
            g.M = BB; g.N = NC; g.zc = 1;
            g.C = d_g; g.ldc = NC; g.Cz = 0;
            g.add0 = d_s; g.add0z = 0;
            g.add1 = d_s + GS; g.add2 = d_s + 2LL * GS;
            g.bias = cb; g.biasz = 0; g.biasCompact = 1;
            mma_stage<32>(g, sb);
        }
        gsync();
        gate_stagef(d_g, 0, 1, d_ctxf_h, d_ctxf_l, (unsigned*)0, (unsigned*)0);
        gsync();

        { // ctx update 1
            MGP g = {};
            g.Ah = d_ctxf_h; g.Al = d_ctxf_l; g.Az = 0;
            g.Bh = d_cWhhf_h; g.Bl = d_cWhhf_l; g.Bz = 0;
            g.M = BB; g.N = NC; g.zc = 1;
            g.C = d_g; g.ldc = NC; g.Cz = 0;
            g.add0 = d_sn; g.add0z = 0;
            g.add1 = d_s + GS; g.add2 = d_s + 2LL * GS;
            g.bias = cb; g.biasz = 0; g.biasCompact = 1;
            mma_stage<32>(g, sb);
        }
        gsync();
        gate_stagef(d_g, 0, 1, d_ctxf_h + ASLAB, d_ctxf_l + ASLAB,
                    (unsigned*)0, (unsigned*)0);
        gsync();

        { // ctx update 2
            MGP g = {};
            g.Ah = d_ctxf_h + 1LL * ASLAB; g.Al = d_ctxf_l + 1LL * ASLAB; g.Az = 0;
            g.Bh = d_cWhhf_h; g.Bl = d_cWhhf_l; g.Bz = 0;
            g.M = BB; g.N = NC; g.zc = 1;
            g.C = d_g; g.ldc = NC; g.Cz = 0;
            g.add0 = d_sn; g.add0z = 0;
            g.add1 = d_sn + GS; g.add2 = d_s + 2LL * GS;
            g.bias = cb; g.biasz = 0; g.biasCompact = 1;
            mma_stage<32>(g, sb);
        }
        gsync();
        gate_stagef(d_g, 0, 1, d_ctxf_h + 2LL * ASLAB, d_ctxf_l + 2LL * ASLAB,
                    (unsigned*)0, (unsigned*)0);
        gsync();

        { // g2[i] = ctx[i] @ W2ih[i][:, :1024]^T + h2[i] @ W2hh[i]^T + C2[i][ptr]
            MGP g = {};
            g.Ah = d_ctxf_h; g.Al = d_ctxf_l; g.Az = ASLAB;
            g.Bh = d_W2ihf_h; g.Bl = d_W2ihf_l; g.Bz = WZS;
            g.A2h = d_h2f_h; g.A2l = d_h2f_l; g.A2z = ASLAB;
            g.B2h = d_W2hhf_h; g.B2l = d_W2hhf_l; g.B2z = WZS;
            g.M = BB; g.N = NC; g.zc = 3;
            g.C = d_g; g.ldc = NC; g.Cz = GS;
            g.add0 = d_C2 + (long long)ptr * GS; g.add0z = 16LL * GS;
            mma_stage<64>(g, sb);
        }
        gsync();
        gate_stagef(d_g, GS, 3, d_h2f_h, d_h2f_l, (unsigned*)0, (unsigned*)0);
        gsync();

        { // out[i][:,t,:] = (uold[i] + h2[i]) @ outW[i]^T + outb[i]
            MGP g = {};
            g.Ah = d_uof_h; g.Al = d_uof_l; g.Az = ASLAB;
            g.Bh = d_outWf_h; g.Bl = d_outWf_l; g.Bz = 32LL * 4096;
            g.A2h = d_h2f_h; g.A2l = d_h2f_l; g.A2z = ASLAB;
            g.B2h = d_outWf_h; g.B2l = d_outWf_l; g.B2z = 32LL * 4096;
            g.M = BB; g.N = VV; g.zc = 3;
            g.C = out + (long long)t * VV; g.ldc = (long long)TT * VV;
            g.Cz = (long long)BB * TT * VV;
            g.bias = outb; g.biasz = VV;
            mma_stage<32>(g, sb);
        }
        gsync();
    }
}

// ---------------- host ----------------
extern "C" void kernel_launch(void* const* d_in, const int* in_sizes, int n_in,
                              void* d_out, int out_size)
{
    (void)in_sizes; (void)n_in; (void)out_size;
    mega_kernel<<<NBLK, NTHR>>>(
        (const float*)d_in[0],  (const float*)d_in[1],  (const float*)d_in[2],
        (const float*)d_in[3],  (const float*)d_in[4],  (const float*)d_in[5],
        (const float*)d_in[6],  (const float*)d_in[7],  (const float*)d_in[8],
        (const float*)d_in[9],  (const float*)d_in[10], (const float*)d_in[11],
        (const float*)d_in[12], (const float*)d_in[13], (const float*)d_in[14],
        (const int*)d_in[15],   (float*)d_out);
}

// round 16
// speedup vs baseline: 1.3067x; 1.0690x over previous
#include <cuda_runtime.h>
#include <cuda_bf16.h>
#include <cstdint>

// ---------------- problem constants ----------------
#define NBLK 296
#define NTHR 256
#define BB   256
#define NC   3072            // compact gate width (i, gg, o) -- f gate is dead
#define TT   256
#define VV   130
#define BH   (256*1024)
#define GS   (256*3072)
#define ASLAB 131072         // uints per activation fragment slab (256x1024/2)
#define WNF  384             // n-frags per z for 3072-row weight matrices
#define WZS  (WNF*4096)      // uints per z for 3072-row weights
#define SMEM_BYTES 65536

// ---------------- persistent device scratch (fp32) ----------------
__device__ float d_cT   [16*256*512];
__device__ float d_cPrev[16*256*512];
__device__ float d_hid  [16*256*1024];
__device__ float d_A1   [3*16*256*3072];
__device__ float d_CU   [16*256*3072];
__device__ float d_C2   [3*16*256*3072];
__device__ float d_E    [3*130*3072];
__device__ float d_nb1  [3*3072];
__device__ float d_s    [3*256*3072];
__device__ float d_sn   [2*256*3072];
__device__ float d_g    [3*256*3072];

// ---------------- fragment-layout weights (hi/lo split bf16, packed uints) --
__device__ unsigned d_W1hhf_h[3*WZS], d_W1hhf_l[3*WZS];
__device__ unsigned d_cWihf_h[3*WZS], d_cWihf_l[3*WZS];
__device__ unsigned d_cWhhf_h[1*WZS], d_cWhhf_l[1*WZS];
__device__ unsigned d_W2ihf_h[3*WZS], d_W2ihf_l[3*WZS];
__device__ unsigned d_W2hhf_h[3*WZS], d_W2hhf_l[3*WZS];
__device__ unsigned d_outWf_h[3*32*4096], d_outWf_l[3*32*4096];  // padded 32 frags

// ---------------- fragment-layout activations ----------------
__device__ unsigned d_h1f_h [3*ASLAB], d_h1f_l [3*ASLAB];
__device__ unsigned d_h2f_h [3*ASLAB], d_h2f_l [3*ASLAB];
__device__ unsigned d_ctxf_h[3*ASLAB], d_ctxf_l[3*ASLAB];
__device__ unsigned d_uof_h [3*ASLAB], d_uof_l [3*ASLAB];
__device__ unsigned d_unf_h [2*ASLAB], d_unf_l [2*ASLAB];

// ---------------- grid barrier (replay-safe, sense via generation) ----------
__device__ unsigned int g_arrive;
__device__ unsigned int g_gen;

__device__ __forceinline__ void gsync()
{
    __threadfence();
    __syncthreads();
    if (threadIdx.x == 0) {
        volatile unsigned int* vg = &g_gen;
        unsigned int g = *vg;
        if (atomicAdd(&g_arrive, 1u) == (unsigned)(gridDim.x - 1)) {
            g_arrive = 0;
            __threadfence();
            *vg = g + 1u;
        } else {
            while (*vg == g) __nanosleep(32);
        }
        __threadfence();
    }
    __syncthreads();
}

// ---------------- f32x2 helpers (preamble FFMA2 path) ----------------
__device__ __forceinline__ void fma2(unsigned long long &c, unsigned long long a,
                                     unsigned long long b) {
    asm("fma.rn.f32x2 %0, %1, %2, %0;" : "+l"(c) : "l"(a), "l"(b));
}
__device__ __forceinline__ void unpack2(unsigned long long v, float &lo, float &hi) {
    asm("mov.b64 {%0, %1}, %2;" : "=f"(lo), "=f"(hi) : "l"(v));
}
__device__ __forceinline__ unsigned long long dup2(float a) {
    unsigned long long r;
    asm("mov.b64 %0, {%1, %1};" : "=l"(r) : "f"(a));
    return r;
}

// ---------------- mma / async helpers ----------------
__device__ __forceinline__ void mma16816(float* d, const unsigned* a, const unsigned* b) {
    asm volatile("mma.sync.aligned.m16n8k16.row.col.f32.bf16.bf16.f32 "
                 "{%0,%1,%2,%3},{%4,%5,%6,%7},{%8,%9},{%0,%1,%2,%3};"
                 : "+f"(d[0]), "+f"(d[1]), "+f"(d[2]), "+f"(d[3])
                 : "r"(a[0]), "r"(a[1]), "r"(a[2]), "r"(a[3]), "r"(b[0]), "r"(b[1]));
}
__device__ __forceinline__ uint2 lds64(unsigned a) {
    uint2 r;
    asm volatile("ld.shared.v2.u32 {%0,%1},[%2];" : "=r"(r.x), "=r"(r.y) : "r"(a));
    return r;
}
__device__ __forceinline__ void cpasync16(unsigned dst, const void* src) {
    asm volatile("cp.async.cg.shared.global [%0],[%1],16;" :: "r"(dst), "l"(src) : "memory");
}
__device__ __forceinline__ void cpcommit() {
    asm volatile("cp.async.commit_group;" ::: "memory");
}
__device__ __forceinline__ void cpwait2() {
    asm volatile("cp.async.wait_group 2;" ::: "memory");
}

// ---------------- split/pack helpers ----------------
__device__ __forceinline__ void pack_split(float v0, float v1, unsigned& hi, unsigned& lo)
{
    __nv_bfloat16 h0 = __float2bfloat16(v0);
    __nv_bfloat16 h1 = __float2bfloat16(v1);
    __nv_bfloat16 l0 = __float2bfloat16(v0 - __bfloat162float(h0));
    __nv_bfloat16 l1 = __float2bfloat16(v1 - __bfloat162float(h1));
    hi = (unsigned)__bfloat16_as_ushort(h0) | ((unsigned)__bfloat16_as_ushort(h1) << 16);
    lo = (unsigned)__bfloat16_as_ushort(l0) | ((unsigned)__bfloat16_as_ushort(l1) << 16);
}

__device__ __forceinline__ float gatef(float gi, float gg, float go)
{
    float si = 1.f / (1.f + expf(-gi));
    float so = 1.f / (1.f + expf(-go));
    return so * tanhf(si * tanhf(gg));
}

// ================= preamble FFMA2 GEMM (256-thread, 64x128 tile) ============
struct GP {
    const float* A;  long long lda,  Az;
    const float* B;  long long ldb,  Bz;
    int K, M, N, zc, compact, epi;
    float* C; long long ldc, Cz;
    const float* bias; long long biasz; int biasCompact;
};

__device__ __forceinline__ void run_mm(const float* A, long long lda, int M, int m0,
                                       const float* Bb, long long ldb, int N, int n0, int K,
                                       float* As, float* Bs,
                                       unsigned long long (*acc)[4],
                                       int tid, int tx, int ty)
{
    int nIter = K >> 4;
    int rowA = tid >> 2, kqA = (tid & 3) << 2;
    for (int it = 0; it < nIter; it++) {
        int k0 = it << 4;
        float4 ra = (m0 + rowA < M && rowA < 64)
            ? *(const float4*)(A + (long long)(m0 + rowA) * lda + k0 + kqA)
            : make_float4(0.f, 0.f, 0.f, 0.f);
        float4 rb[2];
#pragma unroll
        for (int i = 0; i < 2; i++) {
            int j = tid + 256 * i, row = j >> 2, kq = (j & 3) << 2;
            rb[i] = (n0 + row < N)
                ? *(const float4*)(Bb + (long long)row * ldb + k0 + kq)
                : make_float4(0.f, 0.f, 0.f, 0.f);
        }
        __syncthreads();
        if (rowA < 64) {
            As[(kqA + 0) * 64 + rowA] = ra.x;
            As[(kqA + 1) * 64 + rowA] = ra.y;
            As[(kqA + 2) * 64 + rowA] = ra.z;
            As[(kqA + 3) * 64 + rowA] = ra.w;
        }
#pragma unroll
        for (int i = 0; i < 2; i++) {
            int j = tid + 256 * i, row = j >> 2, kq = (j & 3) << 2;
            Bs[(kq + 0) * 128 + row] = rb[i].x;
            Bs[(kq + 1) * 128 + row] = rb[i].y;
            Bs[(kq + 2) * 128 + row] = rb[i].z;
            Bs[(kq + 3) * 128 + row] = rb[i].w;
        }
        __syncthreads();
#pragma unroll
        for (int kk = 0; kk < 16; kk++) {
            ulonglong2 b01 = *(const ulonglong2*)&Bs[kk * 128 + tx * 8];
            ulonglong2 b23 = *(const ulonglong2*)&Bs[kk * 128 + tx * 8 + 4];
            ulonglong2 ap  = *(const ulonglong2*)&As[kk * 64 + ty * 4];
            float av[4];
            unpack2(ap.x, av[0], av[1]);
            unpack2(ap.y, av[2], av[3]);
#pragma unroll
            for (int mi = 0; mi < 4; mi++) {
                unsigned long long a2 = dup2(av[mi]);
                fma2(acc[mi][0], b01.x, a2);
                fma2(acc[mi][1], b01.y, a2);
                fma2(acc[mi][2], b23.x, a2);
                fma2(acc[mi][3], b23.y, a2);
            }
        }
        __syncthreads();
    }
}

__device__ void gemm_stage(const GP& g, float* As, float* Bs)
{
    int mT = (g.M + 63) >> 6;
    int nT = (g.N + 127) >> 7;
    int total = g.zc * mT * nT;
    int tid = threadIdx.x;
    int tx = tid & 15, ty = tid >> 4;

    for (int tile = blockIdx.x; tile < total; tile += gridDim.x) {
        int z  = tile / (mT * nT);
        int r  = tile - z * (mT * nT);
        int m0 = (r / nT) << 6;
        int n0 = (r % nT) << 7;
        int noff = (g.compact && n0 >= 1024) ? 1024 : 0;

        unsigned long long acc[4][4];
#pragma unroll
        for (int i = 0; i < 4; i++)
#pragma unroll
            for (int j = 0; j < 4; j++) acc[i][j] = 0ull;

        const float* A  = g.A + (long long)z * g.Az;
        const float* Bb = g.B + (long long)z * g.Bz + (long long)(n0 + noff) * g.ldb;
        run_mm(A, g.lda, g.M, m0, Bb, g.ldb, g.N, n0, g.K, As, Bs, acc, tid, tx, ty);

        float* C = g.C + (long long)z * g.Cz;
#pragma unroll
        for (int mi = 0; mi < 4; mi++) {
            int m = m0 + ty * 4 + mi;
            if (m >= g.M) continue;
            float cv[8];
#pragma unroll
            for (int jj = 0; jj < 4; jj++)
                unpack2(acc[mi][jj], cv[2 * jj], cv[2 * jj + 1]);
#pragma unroll
            for (int nj = 0; nj < 8; nj++) {
                int n = n0 + tx * 8 + nj;
                if (n >= g.N) continue;
                float v = cv[nj];
                if (g.bias) v += g.bias[(long long)z * g.biasz + (g.biasCompact ? (n + noff) : n)];
                if (g.epi == 1) v = tanhf(v);
                C[(long long)m * g.ldc + n] = v;
            }
        }
    }
}

// ================= fragment-direct tensor-core GEMM =================
// Warp-private cp.async pipelines: each warp owns an 8KB smem region
// (4 stages x NT*512B) and streams its OWN B fragments. No block barriers
// in the mainloop; ordering via per-thread wait_group + __syncwarp.
// A frag slab layout: uint index = ((mf*64 + ks)*32 + lane)*4 + reg
// B frag layout:      uint index = ((nf*64 + ks)*64 + lane*2 + reg)
struct MGP {
    const unsigned *Ah, *Al;   long long Az;
    const unsigned *Bh, *Bl;   long long Bz;
    const unsigned *A2h, *A2l; long long A2z;
    const unsigned *B2h, *B2l; long long B2z;
    int M, N, zc;                               // K fixed = 1024 (64 slices)
    float* C; long long ldc, Cz;
    const float* add0; long long add0z;
    const float *add1, *add2;
    const float* bias; long long biasz; int biasCompact;
    const float* Eg;  long long Egz;
    const int*  tok;  long long tokz;  int tokstride;
};

// TM=64: 8 warps as 2x4 (NT=4). TM=32: 8 warps as 1x8 (NT=2).
template<int TM>
__device__ __forceinline__ void mma_runp(
    const unsigned* Ah, const unsigned* Al,
    const unsigned* Bh, const unsigned* Bl,
    int m0, int n0, float* d, unsigned sbw, int wm, int wn, int L)
{
    constexpr int NT  = (TM == 64) ? 4 : 2;
    constexpr int NJ  = NT / 2;              // 16B chunks per half per thread
    constexpr unsigned STG = NT * 512;       // stage stride (bytes)
    constexpr unsigned HLF = NT * 256;       // lo-half offset (bytes)

    int mf0 = (m0 >> 4) + wm * 2;
    const unsigned* paH0 = Ah + ((long long)(mf0 + 0) * 64) * 128 + L * 4;
    const unsigned* paH1 = Ah + ((long long)(mf0 + 1) * 64) * 128 + L * 4;
    const unsigned* paL0 = Al + ((long long)(mf0 + 0) * 64) * 128 + L * 4;
    const unsigned* paL1 = Al + ((long long)(mf0 + 1) * 64) * 128 + L * 4;

    // per-thread B chunk map: chunk c covers bytes c*16 of the warp stage
    int nf0 = (n0 >> 3) + wn * NT;
    const unsigned* srcH[NJ];
    const unsigned* srcL[NJ];
    unsigned dch[NJ];
#pragma unroll
    for (int j = 0; j < NJ; j++) {
        int c = L + 32 * j;
        long long fo = (long long)(nf0 + (c >> 4)) * 4096 + (c & 15) * 4;
        srcH[j] = Bh + fo;
        srcL[j] = Bl + fo;
        dch[j] = (unsigned)(c * 16);
    }

#pragma unroll
    for (int s = 0; s < 3; s++) {            // prologue: stages 0..2 (slices 0..2)
#pragma unroll
        for (int j = 0; j < NJ; j++) {
            cpasync16(sbw + s * STG + dch[j],       srcH[j] + s * 64);
            cpasync16(sbw + s * STG + HLF + dch[j], srcL[j] + s * 64);
        }
        cpcommit();
    }
    uint4 ahC0 = *(const uint4*)(paH0);
    uint4 ahC1 = *(const uint4*)(paH1);
    uint4 alC0 = *(const uint4*)(paL0);
    uint4 alC1 = *(const uint4*)(paL1);

    for (int ks = 0; ks < 64; ks++) {
        cpwait2();                           // own groups: stage ks ready
        __syncwarp();                        // cross-lane smem visibility
        if (ks + 3 < 64) {
            unsigned sB = ((unsigned)((ks + 3) & 3)) * STG;
#pragma unroll
            for (int j = 0; j < NJ; j++) {
                cpasync16(sbw + sB + dch[j],       srcH[j] + (ks + 3) * 64);
                cpasync16(sbw + sB + HLF + dch[j], srcL[j] + (ks + 3) * 64);
            }
        }
        cpcommit();                          // always: group alignment

        unsigned sBase = sbw + (unsigned)((ks & 3) * STG);
        uint2 bh[NT], bl[NT];
#pragma unroll
        for (int nt = 0; nt < NT; nt++) {
            bh[nt] = lds64(sBase + nt * 256 + L * 8);
            bl[nt] = lds64(sBase + HLF + nt * 256 + L * 8);
        }
        uint4 ah0 = ahC0, ah1 = ahC1, al0 = alC0, al1 = alC1;
        if (ks < 63) {                       // register-prefetch next A slice
            ahC0 = *(const uint4*)(paH0 + (ks + 1) * 128);
            ahC1 = *(const uint4*)(paH1 + (ks + 1) * 128);
            alC0 = *(const uint4*)(paL0 + (ks + 1) * 128);
            alC1 = *(const uint4*)(paL1 + (ks + 1) * 128);
        }
#pragma unroll
        for (int nt = 0; nt < NT; nt++) {
            float* d0 = d + nt * 4;
            float* d1 = d + (NT + nt) * 4;
            mma16816(d0, (const unsigned*)&ah0, (const unsigned*)&bh[nt]);
            mma16816(d0, (const unsigned*)&ah0, (const unsigned*)&bl[nt]);
            mma16816(d0, (const unsigned*)&al0, (const unsigned*)&bh[nt]);
            mma16816(d1, (const unsigned*)&ah1, (const unsigned*)&bh[nt]);
            mma16816(d1, (const unsigned*)&ah1, (const unsigned*)&bl[nt]);
            mma16816(d1, (const unsigned*)&al1, (const unsigned*)&bh[nt]);
        }
    }
}

template<int TM>
__device__ void mma_stage(const MGP& g, unsigned sb)
{
    constexpr int NT = (TM == 64) ? 4 : 2;
    constexpr int NW = NT * 8;
    int mT = (g.M + TM - 1) / TM;
    int nT = (g.N + 127) >> 7;
    int total = g.zc * mT * nT;
    int tid = threadIdx.x, w = tid >> 5, L = tid & 31;
    int wm = (TM == 64) ? (w >> 2) : 0;
    int wn = (TM == 64) ? (w & 3) : w;
    unsigned sbw = sb + (unsigned)(w * 8192);   // warp-private 8KB region

    for (int tile = blockIdx.x; tile < total; tile += gridDim.x) {
        int z  = tile / (mT * nT);
        int r  = tile - z * (mT * nT);
        int m0 = (r / nT) * TM;
        int n0 = (r % nT) << 7;

        float d[2 * NT * 4];
#pragma unroll
        for (int i = 0; i < 2 * NT * 4; i++) d[i] = 0.f;

        mma_runp<TM>(g.Ah + (long long)z * g.Az, g.Al + (long long)z * g.Az,
                     g.Bh + (long long)z * g.Bz, g.Bl + (long long)z * g.Bz,
                     m0, n0, d, sbw, wm, wn, L);
        if (g.A2h)
            mma_runp<TM>(g.A2h + (long long)z * g.A2z, g.A2l + (long long)z * g.A2z,
                         g.B2h + (long long)z * g.B2z, g.B2l + (long long)z * g.B2z,
                         m0, n0, d, sbw, wm, wn, L);

        float* C = g.C + (long long)z * g.Cz;
#pragma unroll
        for (int mt = 0; mt < 2; mt++) {
            int rbase = m0 + wm * 32 + mt * 16 + (L >> 2);
            int tk0 = 0, tk1 = 0;
            if (g.Eg) {
                tk0 = g.tok[(long long)z * g.tokz + (long long)rbase * g.tokstride];
                tk1 = g.tok[(long long)z * g.tokz + (long long)(rbase + 8) * g.tokstride];
            }
#pragma unroll
            for (int nt = 0; nt < NT; nt++) {
                const float* dd = d + (mt * NT + nt) * 4;
                int cbase = n0 + wn * NW + nt * 8 + (L & 3) * 2;
#pragma unroll
                for (int e = 0; e < 4; e++) {
                    int m = rbase + (e >= 2 ? 8 : 0);
                    int n = cbase + (e & 1);
                    if (n >= g.N || m >= g.M) continue;
                    float v = dd[e];
                    if (g.add0) v += g.add0[(long long)z * g.add0z + (long long)m * g.N + n];
                    if (g.add1) v += g.add1[(long long)m * g.N + n];
                    if (g.add2) v += g.add2[(long long)m * g.N + n];
                    if (g.bias) {
                        int nf = g.biasCompact ? (n + (n >= 1024 ? 1024 : 0)) : n;
                        v += g.bias[(long long)z * g.biasz + nf];
                    }
                    if (g.Eg)
                        v += g.Eg[(long long)z * g.Egz +
                                  (long long)(e >= 2 ? tk1 : tk0) * g.N + n];
                    C[(long long)m * g.ldc + n] = v;
                }
            }
        }
    }
}

// ---------------- elementwise stages (fragment writers) ----------------
__device__ void gate_stagef(const float* gsrc, long long gz, int zc,
                            unsigned* d0h, unsigned* d0l,
                            unsigned* d1h, unsigned* d1l)
{
    int total = zc * ASLAB;
    for (int idx = blockIdx.x * NTHR + threadIdx.x; idx < total; idx += gridDim.x * NTHR) {
        int u = idx & (ASLAB - 1);
        int z = idx >> 17;
        int r = u & 3, l = (u >> 2) & 31, ks = (u >> 7) & 63, mf = u >> 13;
        int m  = mf * 16 + (l >> 2) + (r & 1) * 8;
        int k0 = ks * 16 + ((r >> 1) & 1) * 8 + (l & 3) * 2;
        const float* gp = gsrc + (long long)z * gz + (long long)m * NC;
        float v0 = gatef(gp[k0],     gp[1024 + k0],     gp[2048 + k0]);
        float v1 = gatef(gp[k0 + 1], gp[1024 + k0 + 1], gp[2048 + k0 + 1]);
        unsigned hi, lo;
        pack_split(v0, v1, hi, lo);
        d0h[(long long)z * ASLAB + u] = hi;
        d0l[(long long)z * ASLAB + u] = lo;
        if (d1h) {
            d1h[(long long)z * ASLAB + u] = hi;
            d1l[(long long)z * ASLAB + u] = lo;
        }
    }
}

__device__ void reset_stagef(const float* hid)
{
    for (int u = blockIdx.x * NTHR + threadIdx.x; u < ASLAB; u += gridDim.x * NTHR) {
        int r = u & 3, l = (u >> 2) & 31, ks = (u >> 7) & 63, mf = u >> 13;
        int m  = mf * 16 + (l >> 2) + (r & 1) * 8;
        int k0 = ks * 16 + ((r >> 1) & 1) * 8 + (l & 3) * 2;
        const float* hp = hid + (long long)m * 1024 + k0;
        unsigned hi, lo;
        pack_split(hp[0], hp[1], hi, lo);
#pragma unroll
        for (int z = 0; z < 3; z++) {
            d_h1f_h[z * ASLAB + u] = hi; d_h1f_l[z * ASLAB + u] = lo;
            d_h2f_h[z * ASLAB + u] = hi; d_h2f_l[z * ASLAB + u] = lo;
        }
        d_ctxf_h[2 * ASLAB + u] = hi; d_ctxf_l[2 * ASLAB + u] = lo;
    }
}

__device__ void prep_stage(const float* c)
{
    for (int idx = blockIdx.x * NTHR + threadIdx.x; idx < (16 * 256 * 512);
         idx += gridDim.x * NTHR) {
        int ptr = idx >> 17;
        int rem = idx & 131071;
        int b = rem >> 9, k = rem & 511;
        d_cT[idx] = c[((b << 4) + ptr) * 512 + k];
        int pm = ptr > 0 ? ptr - 1 : 0;
        d_cPrev[idx] = c[((b << 4) + pm) * 512 + k];
    }
}

__device__ void nb1_stage(const float* emb, const float* W1ih, const float* b1)
{
    for (int idx = blockIdx.x * NTHR + threadIdx.x; idx < 3 * 3072;
         idx += gridDim.x * NTHR) {
        int i = idx / 3072, n = idx - (idx / 3072) * 3072;
        int nfull = n + (n >= 1024 ? 1024 : 0);
        const float* e = emb + (long long)i * 130 * 512;            // v = 0 row
        const float* w = W1ih + ((long long)i * 4096 + nfull) * 1024;
        float s = b1[i * 4096 + nfull];
        for (int k = 0; k < 512; k++) s += e[k] * w[k];
        d_nb1[idx] = s;
    }
}

__device__ void convw_frag(const float* src, long long sld, long long sz, int kstep,
                           int zc, int Nvalid, int NF, int compact,
                           unsigned* H, unsigned* Lo)
{
    int total = zc * NF * 4096;
    for (int idx = blockIdx.x * NTHR + threadIdx.x; idx < total;
         idx += gridDim.x * NTHR) {
        int r  = idx & 1;
        int l  = (idx >> 1) & 31;
        int ks = (idx >> 6) & 63;
        int rest = idx >> 12;
        int nf = rest % NF, z = rest / NF;
        int n = nf * 8 + (l >> 2);
        int k = ks * 16 + r * 8 + (l & 3) * 2;
        float v0 = 0.f, v1 = 0.f;
        if (n < Nvalid) {
            int nfull = compact ? (n + (n >= 1024 ? 1024 : 0)) : n;
            const float* p = src + (long long)z * sz + (long long)nfull * sld
                           + k + (long long)z * kstep;
            v0 = p[0]; v1 = p[1];
        }
        unsigned hi, lo;
        pack_split(v0, v1, hi, lo);
        H[idx] = hi; Lo[idx] = lo;
    }
}

// ---------------- the single persistent kernel ----------------
__global__ void __launch_bounds__(NTHR, 2)
mega_kernel(const float* c, const float* W1ih, const float* W1hh, const float* b1,
            const float* cWih, const float* cWhh, const float* cb,
            const float* W2ih, const float* W2hh, const float* b2,
            const float* outW, const float* outb,
            const float* hidW, const float* hidb,
            const float* emb, const int* tgt, float* out)
{
    extern __shared__ __align__(16) char smem_raw[];   // 64KB: 8 warps x 8KB
    float* As = (float*)smem_raw;                      // preamble: 4KB
    float* Bs = (float*)(smem_raw + 4096);             // preamble: 8KB
    unsigned sb;
    asm("{.reg .u64 t; cvta.to.shared.u64 t, %1; cvt.u32.u64 %0, t;}"
        : "=r"(sb) : "l"(smem_raw));

    // ---- phase 0: transpose + notes0 hoist + weight fragment conversion ----
    prep_stage(c);
    nb1_stage(emb, W1ih, b1);
    convw_frag(W1hh, 1024, 4096LL * 1024, 0,    3, 3072, WNF, 1, d_W1hhf_h, d_W1hhf_l);
    convw_frag(cWih, 3072, 0,             1024, 3, 3072, WNF, 1, d_cWihf_h, d_cWihf_l);
    convw_frag(cWhh, 1024, 0,             0,    1, 3072, WNF, 1, d_cWhhf_h, d_cWhhf_l);
    convw_frag(W2ih, 1536, 4096LL * 1536, 0,    3, 3072, WNF, 1, d_W2ihf_h, d_W2ihf_l);
    convw_frag(W2hh, 1024, 4096LL * 1024, 0,    3, 3072, WNF, 1, d_W2hhf_h, d_W2hhf_l);
    convw_frag(outW, 1024, 130LL * 1024,  0,    3, 130,  32,  0, d_outWf_h, d_outWf_l);
    gsync();

    // ---- phase 1: per-bar hoisted GEMMs (FFMA2 path) ----
    { GP g = {};
        g.A = d_cPrev; g.lda = 512; g.B = hidW; g.ldb = 512;
        g.K = 512; g.M = 4096; g.N = 1024; g.zc = 1; g.epi = 1;
        g.C = d_hid; g.ldc = 1024; g.bias = hidb;
        gemm_stage(g, As, Bs); }
    { GP g = {};
        g.A = d_cT; g.lda = 512;
        g.B = W1ih + 512; g.ldb = 1024; g.Bz = 4096LL * 1024;
        g.K = 512; g.M = 4096; g.N = NC; g.zc = 3; g.compact = 1;
        g.C = d_A1; g.ldc = NC; g.Cz = 16LL * GS;
        g.bias = d_nb1; g.biasz = NC;
        gemm_stage(g, As, Bs); }
    { GP g = {};
        g.A = d_cT; g.lda = 512;
        g.B = W1ih + 4096LL * 1024 + 512; g.ldb = 1024;
        g.K = 512; g.M = 4096; g.N = NC; g.zc = 1; g.compact = 1;
        g.C = d_CU; g.ldc = NC;
        g.bias = b1 + 4096; g.biasCompact = 1;
        gemm_stage(g, As, Bs); }
    { GP g = {};
        g.A = d_cT; g.lda = 512;
        g.B = W2ih + 1024; g.ldb = 1536; g.Bz = 4096LL * 1536;
        g.K = 512; g.M = 4096; g.N = NC; g.zc = 3; g.compact = 1;
        g.C = d_C2; g.ldc = NC; g.Cz = 16LL * GS;
        g.bias = b2; g.biasz = 4096; g.biasCompact = 1;
        gemm_stage(g, As, Bs); }
    { GP g = {};
        g.A = emb; g.lda = 512;
        g.B = W1ih + 4096LL * 1024; g.ldb = 1024;
        g.K = 512; g.M = 390; g.N = NC; g.zc = 1; g.compact = 1;
        g.C = d_E; g.ldc = NC;
        gemm_stage(g, As, Bs); }
    gsync();

    // ---- time loop (warp-private pipelined tensor-core path) ----
    for (int t = 0; t < TT; t++) {
        int ptr = t >> 4;
        if ((t & 15) == 0) {
            reset_stagef(d_hid + (long long)ptr * BH);
            gsync();
        }

        { // g = A1[.,ptr] + h1 @ W1hh^T
            MGP g = {};
            g.Ah = d_h1f_h; g.Al = d_h1f_l; g.Az = ASLAB;
            g.Bh = d_W1hhf_h; g.Bl = d_W1hhf_l; g.Bz = WZS;
            g.M = BB; g.N = NC; g.zc = 3;
            g.C = d_g; g.ldc = NC; g.Cz = GS;
            g.add0 = d_A1 + (long long)ptr * GS; g.add0z = 16LL * GS;
            mma_stage<64>(g, sb);
        }
        gsync();
        gate_stagef(d_g, GS, 3, d_h1f_h, d_h1f_l, d_uof_h, d_uof_l);
        gsync();

        { // s[i] = uold[i] @ cWih[:, i*1024:]^T
            MGP g = {};
            g.Ah = d_uof_h; g.Al = d_uof_l; g.Az = ASLAB;
            g.Bh = d_cWihf_h; g.Bl = d_cWihf_l; g.Bz = WZS;
            g.M = BB; g.N = NC; g.zc = 3;
            g.C = d_s; g.ldc = NC; g.Cz = GS;
            mma_stage<64>(g, sb);
        }
        { // gu[i] = E[i][tok] + CU[ptr] + uold[i] @ W1hh[1]^T   (i = 0,1)
            MGP g = {};
            g.Ah = d_uof_h; g.Al = d_uof_l; g.Az = ASLAB;
            g.Bh = d_W1hhf_h + 1LL * WZS; g.Bl = d_W1hhf_l + 1LL * WZS; g.Bz = 0;
            g.M = BB; g.N = NC; g.zc = 2;
            g.C = d_g; g.ldc = NC; g.Cz = GS;
            g.add0 = d_CU + (long long)ptr * GS; g.add0z = 0;
            g.Eg = d_E; g.Egz = 130LL * NC;
            g.tok = tgt + t; g.tokz = 65536; g.tokstride = 256;
            mma_stage<64>(g, sb);
        }
        gsync();
        gate_stagef(d_g, GS, 2, d_unf_h, d_unf_l, (unsigned*)0, (unsigned*)0);
        gsync();

        { // sn[i] = unew[i] @ cWih[:, i*1024:]^T  (i = 0,1)
            MGP g = {};
            g.Ah = d_unf_h; g.Al = d_unf_l; g.Az = ASLAB;
            g.Bh = d_cWihf_h; g.Bl = d_cWihf_l; g.Bz = WZS;
            g.M = BB; g.N = NC; g.zc = 2;
            g.C = d_sn; g.ldc = NC; g.Cz = GS;
            mma_stage<64>(g, sb);
        }
        { // ctx update 0
            MGP g = {};
            g.Ah = d_ctxf_h + 2LL * ASLAB; g.Al = d_ctxf_l + 2LL * ASLAB; g.Az = 0;
            g.Bh = d_cWhhf_h; g.Bl = d_cWhhf_l; g.Bz = 0;
            g.M = BB; g.N = NC; g.zc = 1;
            g.C = d_g; g.ldc = NC; g.Cz = 0;
            g.add0 = d_s; g.add0z = 0;
            g.add1 = d_s + GS; g.add2 = d_s + 2LL * GS;
            g.bias = cb; g.biasz = 0; g.biasCompact = 1;
            mma_stage<32>(g, sb);
        }
        gsync();
        gate_stagef(d_g, 0, 1, d_ctxf_h, d_ctxf_l, (unsigned*)0, (unsigned*)0);
        gsync();

        { // ctx update 1
            MGP g = {};
            g.Ah = d_ctxf_h; g.Al = d_ctxf_l; g.Az = 0;
            g.Bh = d_cWhhf_h; g.Bl = d_cWhhf_l; g.Bz = 0;
            g.M = BB; g.N = NC; g.zc = 1;
            g.C = d_g; g.ldc = NC; g.Cz = 0;
            g.add0 = d_sn; g.add0z = 0;
            g.add1 = d_s + GS; g.add2 = d_s + 2LL * GS;
            g.bias = cb; g.biasz = 0; g.biasCompact = 1;
            mma_stage<32>(g, sb);
        }
        gsync();
        gate_stagef(d_g, 0, 1, d_ctxf_h + ASLAB, d_ctxf_l + ASLAB,
                    (unsigned*)0, (unsigned*)0);
        gsync();

        { // ctx update 2
            MGP g = {};
            g.Ah = d_ctxf_h + 1LL * ASLAB; g.Al = d_ctxf_l + 1LL * ASLAB; g.Az = 0;
            g.Bh = d_cWhhf_h; g.Bl = d_cWhhf_l; g.Bz = 0;
            g.M = BB; g.N = NC; g.zc = 1;
            g.C = d_g; g.ldc = NC; g.Cz = 0;
            g.add0 = d_sn; g.add0z = 0;
            g.add1 = d_sn + GS; g.add2 = d_s + 2LL * GS;
            g.bias = cb; g.biasz = 0; g.biasCompact = 1;
            mma_stage<32>(g, sb);
        }
        gsync();
        gate_stagef(d_g, 0, 1, d_ctxf_h + 2LL * ASLAB, d_ctxf_l + 2LL * ASLAB,
                    (unsigned*)0, (unsigned*)0);
        gsync();

        { // g2[i] = ctx[i] @ W2ih[i][:, :1024]^T + h2[i] @ W2hh[i]^T + C2[i][ptr]
            MGP g = {};
            g.Ah = d_ctxf_h; g.Al = d_ctxf_l; g.Az = ASLAB;
            g.Bh = d_W2ihf_h; g.Bl = d_W2ihf_l; g.Bz = WZS;
            g.A2h = d_h2f_h; g.A2l = d_h2f_l; g.A2z = ASLAB;
            g.B2h = d_W2hhf_h; g.B2l = d_W2hhf_l; g.B2z = WZS;
            g.M = BB; g.N = NC; g.zc = 3;
            g.C = d_g; g.ldc = NC; g.Cz = GS;
            g.add0 = d_C2 + (long long)ptr * GS; g.add0z = 16LL * GS;
            mma_stage<64>(g, sb);
        }
        gsync();
        gate_stagef(d_g, GS, 3, d_h2f_h, d_h2f_l, (unsigned*)0, (unsigned*)0);
        gsync();

        { // out[i][:,t,:] = (uold[i] + h2[i]) @ outW[i]^T + outb[i]
            MGP g = {};
            g.Ah = d_uof_h; g.Al = d_uof_l; g.Az = ASLAB;
            g.Bh = d_outWf_h; g.Bl = d_outWf_l; g.Bz = 32LL * 4096;
            g.A2h = d_h2f_h; g.A2l = d_h2f_l; g.A2z = ASLAB;
            g.B2h = d_outWf_h; g.B2l = d_outWf_l; g.B2z = 32LL * 4096;
            g.M = BB; g.N = VV; g.zc = 3;
            g.C = out + (long long)t * VV; g.ldc = (long long)TT * VV;
            g.Cz = (long long)BB * TT * VV;
            g.bias = outb; g.biasz = VV;
            mma_stage<32>(g, sb);
        }
        gsync();
    }
}

// ---------------- host ----------------
extern "C" void kernel_launch(void* const* d_in, const int* in_sizes, int n_in,
                              void* d_out, int out_size)
{
    (void)in_sizes; (void)n_in; (void)out_size;
    cudaFuncSetAttribute(mega_kernel,
                         cudaFuncAttributeMaxDynamicSharedMemorySize, SMEM_BYTES);
    mega_kernel<<<NBLK, NTHR, SMEM_BYTES>>>(
        (const float*)d_in[0],  (const float*)d_in[1],  (const float*)d_in[2],
        (const float*)d_in[3],  (const float*)d_in[4],  (const float*)d_in[5],
        (const float*)d_in[6],  (const float*)d_in[7],  (const float*)d_in[8],
        (const float*)d_in[9],  (const float*)d_in[10], (const float*)d_in[11],
        (const float*)d_in[12], (const float*)d_in[13], (const float*)d_in[14],
        (const int*)d_in[15],   (float*)d_out);
}